// round 12
// baseline (speedup 1.0000x reference)
#include <cuda_runtime.h>
#include <math.h>

// Problem constants
static const int BB = 64, TT = 256, VV = 65, EE = 384, HH = 6, LLAY = 6, DD = 64, FF = 1536;
static const int NTOK = BB * TT; // 16384
static const int QKVM = 3 * EE;  // 1152
static const int GEMM_GRID = 296; // 148 SMs * 2 CTAs/SM

// ---------------- scratch ----------------------------------------------------
__device__ __align__(16) float g_x  [16384 * 384];
__device__ __align__(16) float g_h  [16384 * 384];    // packed LN output
__device__ __align__(16) float g_qkv[16384 * 1152];   // natural, stride 1152
__device__ __align__(16) float g_att[16384 * 384];    // packed
__device__ __align__(16) float g_f  [16384 * 1536];   // packed FFN / head scratch
__device__ __align__(16) float g_logits[16384 * 65];
__device__ __align__(16) float g_loss[1];
__device__ __align__(16) float g_pw[10665984];

// ---------------- helpers ----------------------------------------------------
__device__ __forceinline__ float f2tf(float f) {
    unsigned u;
    asm("cvt.rna.tf32.f32 %0, %1;" : "=r"(u) : "f"(f));
    return __uint_as_float(u);
}
// packed-A index for element (row, col) of an [N x Kc] activation matrix
__device__ __forceinline__ int pk_a(int row, int col, int Kc) {
    return ((row >> 4) * (Kc >> 3) + (col >> 3)) * 128
         + ((row & 7) * 4 + (col & 3)) * 4 + ((row >> 3) & 1) + ((col >> 2) & 1) * 2;
}
// packed-B index for element (k, m) of a [K x M] weight matrix
__device__ __forceinline__ int pk_b(int k, int m, int M) {
    return ((k >> 3) * (M >> 3) + (m >> 3)) * 64
         + ((m & 7) * 4 + (k & 3)) * 2 + ((k >> 2) & 1);
}
__device__ __forceinline__ void cpa16(unsigned s, const float* g) {
    asm volatile("cp.async.cg.shared.global [%0], [%1], 16;" :: "r"(s), "l"(g));
}

// ---------------- weight pre-pack --------------------------------------------
__global__ void k_packW(const float* __restrict__ W, float* __restrict__ PW,
                        int K, int M) {
    int i = blockIdx.x * blockDim.x + threadIdx.x;
    int tot = K * M;
    if (i >= tot) return;
    const float* w = W + (size_t)blockIdx.y * tot;
    float* pw = PW + (size_t)blockIdx.y * tot;
    int k = i / M, m = i - k * M;
    pw[pk_b(k, m, M)] = f2tf(w[i]);
}

// fused QKV pack: [E, 1152] from Wq|Wk|Wv each [L,E,E]
__global__ void k_packQKV(const float* __restrict__ Wq, const float* __restrict__ Wk,
                          const float* __restrict__ Wv, float* __restrict__ PW) {
    int i = blockIdx.x * blockDim.x + threadIdx.x;
    const int tot = EE * QKVM;
    if (i >= tot) return;
    int l = blockIdx.y;
    int k = i / QKVM, m = i - k * QKVM;
    float v;
    if (m < EE)            v = Wq[(size_t)l * EE * EE + (size_t)k * EE + m];
    else if (m < 2 * EE)   v = Wk[(size_t)l * EE * EE + (size_t)k * EE + (m - EE)];
    else                   v = Wv[(size_t)l * EE * EE + (size_t)k * EE + (m - 2 * EE)];
    PW[(size_t)l * tot + pk_b(k, m, QKVM)] = f2tf(v);
}

// LM head pack: [384, 65] -> padded packed [384, 128]
__global__ void k_packWlm(const float* __restrict__ W, float* __restrict__ PW) {
    int i = blockIdx.x * blockDim.x + threadIdx.x;
    if (i >= EE * 128) return;
    int k = i / 128, m = i - k * 128;
    float v = (m < VV) ? W[(size_t)k * VV + m] : 0.f;
    PW[pk_b(k, m, 128)] = f2tf(v);
}

// ---------------- embedding --------------------------------------------------
__global__ void k_embed(const int* __restrict__ idx, const float* __restrict__ tok,
                        const float* __restrict__ pos, float* __restrict__ x) {
    int i = blockIdx.x * blockDim.x + threadIdx.x;
    if (i >= NTOK * EE) return;
    int n = i / EE, e = i - n * EE;
    int t = n % TT;
    x[i] = tok[idx[n] * EE + e] + pos[t * EE + e];
}

// ---------------- LayerNorm (natural in, packed tf32 out) --------------------
__global__ void k_ln(const float* __restrict__ x, const float* __restrict__ g,
                     const float* __restrict__ b, float* __restrict__ y) {
    int warp = threadIdx.x >> 5, lane = threadIdx.x & 31;
    int row = blockIdx.x * 8 + warp;
    if (row >= NTOK) return;
    const float4* xr = (const float4*)(x + (size_t)row * EE);
    float4 v[3];
#pragma unroll
    for (int i = 0; i < 3; i++) v[i] = xr[lane + i * 32];
    float s = 0.f, s2 = 0.f;
#pragma unroll
    for (int i = 0; i < 3; i++) {
        s  += v[i].x + v[i].y + v[i].z + v[i].w;
        s2 += v[i].x * v[i].x + v[i].y * v[i].y + v[i].z * v[i].z + v[i].w * v[i].w;
    }
#pragma unroll
    for (int off = 16; off > 0; off >>= 1) {
        s  += __shfl_xor_sync(0xffffffffu, s,  off);
        s2 += __shfl_xor_sync(0xffffffffu, s2, off);
    }
    float mu = s * (1.f / EE);
    float var = s2 * (1.f / EE) - mu * mu;
    float rs = rsqrtf(var + 1e-5f);
    const float4* gr = (const float4*)g;
    const float4* br = (const float4*)b;
#pragma unroll
    for (int i = 0; i < 3; i++) {
        float4 gg = gr[lane + i * 32], bb = br[lane + i * 32];
        float o0 = (v[i].x - mu) * rs * gg.x + bb.x;
        float o1 = (v[i].y - mu) * rs * gg.y + bb.y;
        float o2 = (v[i].z - mu) * rs * gg.z + bb.z;
        float o3 = (v[i].w - mu) * rs * gg.w + bb.w;
        int cb = (lane + i * 32) * 4;
        y[pk_a(row, cb + 0, EE)] = f2tf(o0);
        y[pk_a(row, cb + 1, EE)] = f2tf(o1);
        y[pk_a(row, cb + 2, EE)] = f2tf(o2);
        y[pk_a(row, cb + 3, EE)] = f2tf(o3);
    }
}

// ---------------- persistent tf32 tensor-core GEMM ---------------------------
// C[N,M] = A[N,K] @ W[K,M]; A,W pre-packed tf32 fragment layout in global.
// 128x128x32 block tile, 8 warps (2x4), warp tile 64x32, m16n8k8 mma.
// Persistent grid-stride loop over tiles (kills wave quantization).
// 3-stage cp.async ring; commit_group EVERY iteration so wait_group 1
// always guarantees slab kb arrival (fixes latent tail race).
// flags: 1=relu, 2=packed output.
__global__ void __launch_bounds__(256, 2) k_gemm_p(
    const float* __restrict__ PA, const float* __restrict__ PB,
    const float* __restrict__ bias, const float* __restrict__ res,
    float* __restrict__ C, int K, int M, int flags, int nTileM, int nTiles)
{
    extern __shared__ float smem[];
    const int tid  = threadIdx.x;
    const int lane = tid & 31, warp = tid >> 5;
    const int wm = warp & 1, wn = warp >> 1;
    const int gid = lane >> 2, tig = lane & 3;
    const int K8 = K >> 3, M8 = M >> 3;
    const int KB = K >> 5;

    // per-thread channel decomposition (tile-independent parts)
    int offA[4], offB[4];
    unsigned sA[4], sB[4];
#pragma unroll
    for (int i = 0; i < 4; i++) {
        int ch = tid + i * 256;
        int mt = ch >> 7, kt = (ch >> 5) & 3, c4 = ch & 31;
        sA[i] = (unsigned)(((mt * 4 + kt) * 128 + c4 * 4) * 4);
        offA[i] = (mt * K8 + kt) * 128 + c4 * 4;
        int bkt = ch >> 8, nt = (ch >> 4) & 15, d4 = ch & 15;
        sB[i] = (unsigned)((4096 + (bkt * 16 + nt) * 64 + d4 * 4) * 4);
        offB[i] = (bkt * M8 + nt) * 64 + d4 * 4;
    }
    unsigned smem_u = (unsigned)__cvta_generic_to_shared(smem);
    const bool relu = (flags & 1), pko = (flags & 2);

    for (int t = blockIdx.x; t < nTiles; t += gridDim.x) {
        const int m0 = (t % nTileM) << 7;
        const int n0 = (t / nTileM) << 7;
        const float* Abase = PA + (size_t)n0 * K;       // row-block base
        const float* Bbase = PB + (size_t)m0 * 8;       // col-block base

        auto issue = [&](int ks, int buf) {
            unsigned base = smem_u + (unsigned)buf * 8192u * 4u;
#pragma unroll
            for (int i = 0; i < 4; i++) cpa16(base + sA[i], Abase + offA[i] + ks * 512);
#pragma unroll
            for (int i = 0; i < 4; i++) cpa16(base + sB[i], Bbase + offB[i] + (size_t)ks * 32 * M);
        };

        float acc[4][4][4];
#pragma unroll
        for (int a = 0; a < 4; a++)
#pragma unroll
            for (int b = 0; b < 4; b++)
#pragma unroll
                for (int c = 0; c < 4; c++) acc[a][b][c] = 0.f;

        issue(0, 0);
        asm volatile("cp.async.commit_group;" ::: "memory");
        issue(1, 1);
        asm volatile("cp.async.commit_group;" ::: "memory");

        int p = 0;
        for (int kb = 0; kb < KB; kb++) {
            asm volatile("cp.async.wait_group 1;" ::: "memory");
            __syncthreads();
            if (kb + 2 < KB) issue(kb + 2, (kb + 2) % 3);
            asm volatile("cp.async.commit_group;" ::: "memory");

            const float* as = smem + p * 8192;
            const float* bs = as + 4096;
#pragma unroll
            for (int kt = 0; kt < 4; kt++) {
                unsigned af[4][4], bf[4][2];
#pragma unroll
                for (int mi = 0; mi < 4; mi++) {
                    float4 v = *(const float4*)&as[((((wm * 4 + mi) * 4) + kt) << 7) + (lane << 2)];
                    af[mi][0] = __float_as_uint(v.x); af[mi][1] = __float_as_uint(v.y);
                    af[mi][2] = __float_as_uint(v.z); af[mi][3] = __float_as_uint(v.w);
                }
#pragma unroll
                for (int ni = 0; ni < 4; ni++) {
                    float2 v = *(const float2*)&bs[(((kt * 16) + (wn * 4 + ni)) << 6) + (lane << 1)];
                    bf[ni][0] = __float_as_uint(v.x); bf[ni][1] = __float_as_uint(v.y);
                }
#pragma unroll
                for (int mi = 0; mi < 4; mi++)
#pragma unroll
                    for (int ni = 0; ni < 4; ni++) {
                        asm volatile(
                            "mma.sync.aligned.m16n8k8.row.col.f32.tf32.tf32.f32 "
                            "{%0,%1,%2,%3}, {%4,%5,%6,%7}, {%8,%9}, {%0,%1,%2,%3};"
                            : "+f"(acc[mi][ni][0]), "+f"(acc[mi][ni][1]),
                              "+f"(acc[mi][ni][2]), "+f"(acc[mi][ni][3])
                            : "r"(af[mi][0]), "r"(af[mi][1]), "r"(af[mi][2]), "r"(af[mi][3]),
                              "r"(bf[ni][0]), "r"(bf[ni][1]));
                    }
            }
            p = (p == 2) ? 0 : p + 1;
        }
        asm volatile("cp.async.wait_group 0;" ::: "memory");

        // epilogue
#pragma unroll
        for (int mi = 0; mi < 4; mi++) {
            int row = n0 + (wm << 6) + (mi << 4) + gid;
#pragma unroll
            for (int ni = 0; ni < 4; ni++) {
                int col = m0 + (wn << 5) + (ni << 3) + (tig << 1);
                float b0 = 0.f, b1 = 0.f;
                if (bias) { b0 = bias[col]; b1 = bias[col + 1]; }
                float v0 = acc[mi][ni][0] + b0;
                float v1 = acc[mi][ni][1] + b1;
                float v2 = acc[mi][ni][2] + b0;
                float v3 = acc[mi][ni][3] + b1;
                if (res) {
                    const float* r0 = res + (size_t)row * M + col;
                    const float* r1 = res + (size_t)(row + 8) * M + col;
                    v0 += r0[0]; v1 += r0[1]; v2 += r1[0]; v3 += r1[1];
                }
                if (relu) {
                    v0 = fmaxf(v0, 0.f); v1 = fmaxf(v1, 0.f);
                    v2 = fmaxf(v2, 0.f); v3 = fmaxf(v3, 0.f);
                }
                if (pko) {
                    C[pk_a(row,     col,     M)] = f2tf(v0);
                    C[pk_a(row,     col + 1, M)] = f2tf(v1);
                    C[pk_a(row + 8, col,     M)] = f2tf(v2);
                    C[pk_a(row + 8, col + 1, M)] = f2tf(v3);
                } else {
                    *(float2*)(C + (size_t)row * M + col)       = make_float2(v0, v1);
                    *(float2*)(C + (size_t)(row + 8) * M + col) = make_float2(v2, v3);
                }
            }
        }
        __syncthreads();   // smem reuse barrier before next tile's prologue
    }
}

// ---------------- causal attention: fused-QKV in (stride 1152), 2-key ILP ----
__global__ void __launch_bounds__(256) k_attn(
    const float* __restrict__ QKV, float* __restrict__ O)
{
    __shared__ float Ks[64][64];
    __shared__ float Vs[64][64];
    const int hd = blockIdx.x, b = blockIdx.y;
    const int tq = threadIdx.x;
    const float scale = 0.125f;

    float4 q4[16], o4[16];
    const float4* qr = (const float4*)(QKV + (size_t)(b * TT + tq) * QKVM + hd * DD);
#pragma unroll
    for (int i = 0; i < 16; i++) { q4[i] = qr[i]; o4[i] = make_float4(0.f, 0.f, 0.f, 0.f); }
    float m = -INFINITY, l = 0.f;

    for (int c = 0; c < 4; c++) {
#pragma unroll
        for (int i = 0; i < 4; i++) {
            int idx = threadIdx.x + i * 256;
            int r = idx >> 4, d4 = idx & 15;
            size_t goff = (size_t)(b * TT + c * 64 + r) * QKVM + hd * DD;
            ((float4*)&Ks[r][0])[d4] = ((const float4*)(QKV + goff + EE))[d4];
            ((float4*)&Vs[r][0])[d4] = ((const float4*)(QKV + goff + 2 * EE))[d4];
        }
        __syncthreads();
        int rel = tq - c * 64;
        if (rel >= 0) {
            int kend = rel + 1; if (kend > 64) kend = 64;
            int kk = 0;
            for (; kk + 1 < kend; kk += 2) {
                const float4* kr0 = (const float4*)&Ks[kk][0];
                const float4* kr1 = (const float4*)&Ks[kk + 1][0];
                float s0 = 0.f, s1 = 0.f;
#pragma unroll
                for (int i = 0; i < 16; i++) {
                    float4 k0 = kr0[i], k1 = kr1[i], qv = q4[i];
                    s0 += qv.x * k0.x + qv.y * k0.y + qv.z * k0.z + qv.w * k0.w;
                    s1 += qv.x * k1.x + qv.y * k1.y + qv.z * k1.z + qv.w * k1.w;
                }
                s0 *= scale; s1 *= scale;
                float mn = fmaxf(m, fmaxf(s0, s1));
                float al = __expf(m - mn);
                float p0 = __expf(s0 - mn);
                float p1 = __expf(s1 - mn);
                l = l * al + p0 + p1;
                const float4* vr0 = (const float4*)&Vs[kk][0];
                const float4* vr1 = (const float4*)&Vs[kk + 1][0];
#pragma unroll
                for (int i = 0; i < 16; i++) {
                    float4 v0 = vr0[i], v1 = vr1[i];
                    o4[i].x = o4[i].x * al + p0 * v0.x + p1 * v1.x;
                    o4[i].y = o4[i].y * al + p0 * v0.y + p1 * v1.y;
                    o4[i].z = o4[i].z * al + p0 * v0.z + p1 * v1.z;
                    o4[i].w = o4[i].w * al + p0 * v0.w + p1 * v1.w;
                }
                m = mn;
            }
            if (kk < kend) {
                const float4* kr = (const float4*)&Ks[kk][0];
                float s = 0.f;
#pragma unroll
                for (int i = 0; i < 16; i++) {
                    float4 kv = kr[i];
                    s += q4[i].x * kv.x + q4[i].y * kv.y + q4[i].z * kv.z + q4[i].w * kv.w;
                }
                s *= scale;
                float mn = fmaxf(m, s);
                float pp = __expf(s - mn);
                float al = __expf(m - mn);
                l = l * al + pp;
                const float4* vr = (const float4*)&Vs[kk][0];
#pragma unroll
                for (int i = 0; i < 16; i++) {
                    float4 vv = vr[i];
                    o4[i].x = o4[i].x * al + pp * vv.x;
                    o4[i].y = o4[i].y * al + pp * vv.y;
                    o4[i].z = o4[i].z * al + pp * vv.z;
                    o4[i].w = o4[i].w * al + pp * vv.w;
                }
                m = mn;
            }
        }
        __syncthreads();
    }
    float inv = 1.f / l;
    int rowR = b * TT + tq;
#pragma unroll
    for (int i = 0; i < 16; i++) {
        int cb = hd * DD + i * 4;
        O[pk_a(rowR, cb + 0, EE)] = f2tf(o4[i].x * inv);
        O[pk_a(rowR, cb + 1, EE)] = f2tf(o4[i].y * inv);
        O[pk_a(rowR, cb + 2, EE)] = f2tf(o4[i].z * inv);
        O[pk_a(rowR, cb + 3, EE)] = f2tf(o4[i].w * inv);
    }
}

// ---------------- LM head compact: padded [N,128] -> [N,65] + bias -----------
__global__ void k_head_compact(const float* __restrict__ C128,
                               const float* __restrict__ blm,
                               float* __restrict__ logits) {
    int i = blockIdx.x * blockDim.x + threadIdx.x;
    if (i >= NTOK * VV) return;
    int n = i / VV, m = i - n * VV;
    logits[i] = C128[(size_t)n * 128 + m] + blm[m];
}

// ---------------- loss -------------------------------------------------------
__global__ void k_zero(float* loss) { *loss = 0.f; }

__global__ void k_loss(const float* __restrict__ logits, const int* __restrict__ tgt,
                       float* __restrict__ loss) {
    int warp = threadIdx.x >> 5, lane = threadIdx.x & 31;
    int row = blockIdx.x * 8 + warp;
    if (row >= NTOK) return;
    const float* lr = logits + (size_t)row * VV;
    float x0 = (lane < VV)      ? lr[lane]      : -INFINITY;
    float x1 = (lane + 32 < VV) ? lr[lane + 32] : -INFINITY;
    float x2 = (lane + 64 < VV) ? lr[lane + 64] : -INFINITY;
    float mx = fmaxf(x0, fmaxf(x1, x2));
#pragma unroll
    for (int off = 16; off > 0; off >>= 1) mx = fmaxf(mx, __shfl_xor_sync(0xffffffffu, mx, off));
    float se = 0.f;
    if (lane < VV)      se += expf(x0 - mx);
    if (lane + 32 < VV) se += expf(x1 - mx);
    if (lane + 64 < VV) se += expf(x2 - mx);
#pragma unroll
    for (int off = 16; off > 0; off >>= 1) se += __shfl_xor_sync(0xffffffffu, se, off);
    if (lane == 0) {
        float lt = lr[tgt[row]];
        atomicAdd(loss, mx + logf(se) - lt);
    }
}

__global__ void k_final(const float* __restrict__ loss, float* __restrict__ out) {
    out[0] = *loss * (1.f / NTOK);
}

// ---------------- host -------------------------------------------------------
extern "C" void kernel_launch(void* const* d_in, const int* in_sizes, int n_in,
                              void* d_out, int out_size) {
    const int*   idx  = (const int*)  d_in[0];
    const int*   tgt  = (const int*)  d_in[1];
    const float* tok  = (const float*)d_in[2];
    const float* pos  = (const float*)d_in[3];
    const float* Wq   = (const float*)d_in[4];
    const float* Wk   = (const float*)d_in[5];
    const float* Wv   = (const float*)d_in[6];
    const float* Wo   = (const float*)d_in[7];
    const float* bo   = (const float*)d_in[8];
    const float* W1   = (const float*)d_in[9];
    const float* b1   = (const float*)d_in[10];
    const float* W2   = (const float*)d_in[11];
    const float* b2w  = (const float*)d_in[12];
    const float* ln1g = (const float*)d_in[13];
    const float* ln1b = (const float*)d_in[14];
    const float* ln2g = (const float*)d_in[15];
    const float* ln2b = (const float*)d_in[16];
    const float* lnfg = (const float*)d_in[17];
    const float* lnfb = (const float*)d_in[18];
    const float* Wlm  = (const float*)d_in[19];
    const float* blm  = (const float*)d_in[20];

    float *x, *h, *qkv, *att, *f, *glog, *gloss, *pw;
    cudaGetSymbolAddress((void**)&x,    g_x);
    cudaGetSymbolAddress((void**)&h,    g_h);
    cudaGetSymbolAddress((void**)&qkv,  g_qkv);
    cudaGetSymbolAddress((void**)&att,  g_att);
    cudaGetSymbolAddress((void**)&f,    g_f);
    cudaGetSymbolAddress((void**)&glog, g_logits);
    cudaGetSymbolAddress((void**)&gloss, g_loss);
    cudaGetSymbolAddress((void**)&pw,   g_pw);

    static int smem_set = 0;
    if (!smem_set) {
        cudaFuncSetAttribute(k_gemm_p, cudaFuncAttributeMaxDynamicSharedMemorySize, 98304);
        smem_set = 1;
    }

    const size_t EExEE = (size_t)EE * EE, EExFF = (size_t)EE * FF, EExQ = (size_t)EE * QKVM;
    float* pqkv = pw;
    float* pwo  = pqkv + (size_t)LLAY * EExQ;
    float* pw1  = pwo  + (size_t)LLAY * EExEE;
    float* pw2  = pw1  + (size_t)LLAY * EExFF;
    float* pwlm = pw2  + (size_t)LLAY * EExFF;

    k_packQKV<<<dim3((EE * QKVM + 255) / 256, LLAY), 256>>>(Wq, Wk, Wv, pqkv);
    k_packW<<<dim3((EE * EE + 255) / 256, LLAY), 256>>>(Wo, pwo, EE, EE);
    k_packW<<<dim3((EE * FF + 255) / 256, LLAY), 256>>>(W1, pw1, EE, FF);
    k_packW<<<dim3((EE * FF + 255) / 256, LLAY), 256>>>(W2, pw2, FF, EE);
    k_packWlm<<<(EE * 128 + 255) / 256, 256>>>(Wlm, pwlm);

    float* outf   = (float*)d_out;
    float* logits = (out_size >= NTOK * VV) ? outf : glog;

    k_embed<<<(NTOK * EE + 255) / 256, 256>>>(idx, tok, pos, x);

    const int nRow = NTOK / 128;              // 128
    const int tQ = (QKVM / 128) * nRow;       // 1152
    const int tE = (EE / 128) * nRow;         // 384
    const int tF = (FF / 128) * nRow;         // 1536
    dim3 gLN(NTOK / 8);
    const int DSM = 98304;

    for (int l = 0; l < LLAY; l++) {
        k_ln<<<gLN, 256>>>(x, ln1g + l * EE, ln1b + l * EE, h);
        k_gemm_p<<<GEMM_GRID, 256, DSM>>>(h, pqkv + (size_t)l * EExQ, nullptr, nullptr,
                                          qkv, EE, QKVM, 0, QKVM / 128, tQ);
        k_attn<<<dim3(HH, BB), 256>>>(qkv, att);
        k_gemm_p<<<GEMM_GRID, 256, DSM>>>(att, pwo + (size_t)l * EExEE, bo + l * EE, x,
                                          x, EE, EE, 0, EE / 128, tE);
        k_ln<<<gLN, 256>>>(x, ln2g + l * EE, ln2b + l * EE, h);
        k_gemm_p<<<GEMM_GRID, 256, DSM>>>(h, pw1 + (size_t)l * EExFF, b1 + l * FF, nullptr,
                                          f, EE, FF, 1 | 2, FF / 128, tF);
        k_gemm_p<<<GEMM_GRID, 256, DSM>>>(f, pw2 + (size_t)l * EExFF, b2w + l * EE, x,
                                          x, FF, EE, 0, EE / 128, tE);
    }

    k_ln<<<gLN, 256>>>(x, lnfg, lnfb, h);
    k_gemm_p<<<GEMM_GRID, 256, DSM>>>(h, pwlm, nullptr, nullptr, f, EE, 128, 0, 1, nRow);
    k_head_compact<<<(NTOK * VV + 255) / 256, 256>>>(f, blm, logits);

    if (out_size == 1 || out_size > NTOK * VV) {
        k_zero<<<1, 1>>>(gloss);
        k_loss<<<NTOK / 8, 256>>>(logits, tgt, gloss);
        float* ldst = (out_size == 1) ? outf : (outf + NTOK * VV);
        k_final<<<1, 1>>>(gloss, ldst);
    }
}

// round 13
// speedup vs baseline: 1.3476x; 1.3476x over previous
#include <cuda_runtime.h>
#include <cuda_fp16.h>
#include <math.h>

// Problem constants
static const int BB = 64, TT = 256, VV = 65, EE = 384, HH = 6, LLAY = 6, DD = 64, FF = 1536;
static const int NTOK = BB * TT; // 16384
static const int QKVM = 3 * EE;  // 1152
static const int GEMM_GRID = 296;

// ---------------- scratch ----------------------------------------------------
__device__ __align__(16) float  g_x   [16384 * 384];
__device__ __align__(16) __half g_h16 [16384 * 384];    // packed LN output
__device__ __align__(16) float  g_qkv [16384 * 1152];   // natural fp32
__device__ __align__(16) __half g_att16[16384 * 384];   // packed
__device__ __align__(16) __half g_f16 [16384 * 1536];   // packed FFN mid
__device__ __align__(16) float  g_hd  [16384 * 128];    // head GEMM out
__device__ __align__(16) float  g_logits[16384 * 65];
__device__ __align__(16) float  g_loss[1];
__device__ __align__(16) __half g_pw16[10665984];

// ---------------- fp16 m16n8k16 fragment-packed indices ----------------------
// A[N x K] element (row, col): 16x16 tiles, per-thread 8 halves contiguous.
__device__ __forceinline__ size_t pk_a16(int row, int col, int K) {
    return ((size_t)(row >> 4) * (K >> 4) + (col >> 4)) * 256
         + ((row & 7) * 4 + ((col & 7) >> 1)) * 8
         + (((col >> 3) & 1) * 2 + ((row >> 3) & 1)) * 2 + (col & 1);
}
// B[K x M] element (k, m): 16k x 8m tiles, per-thread 4 halves contiguous.
__device__ __forceinline__ size_t pk_b16(int k, int m, int M) {
    return ((size_t)(k >> 4) * (M >> 3) + (m >> 3)) * 128
         + ((m & 7) * 4 + ((k & 7) >> 1)) * 4
         + ((k >> 3) & 1) * 2 + (k & 1);
}
__device__ __forceinline__ void cpa16(unsigned s, const void* g) {
    asm volatile("cp.async.cg.shared.global [%0], [%1], 16;" :: "r"(s), "l"(g));
}

// ---------------- weight pre-pack --------------------------------------------
__global__ void k_packW(const float* __restrict__ W, __half* __restrict__ PW,
                        int K, int M) {
    int i = blockIdx.x * blockDim.x + threadIdx.x;
    int tot = K * M;
    if (i >= tot) return;
    const float* w = W + (size_t)blockIdx.y * tot;
    __half* pw = PW + (size_t)blockIdx.y * tot;
    int k = i / M, m = i - k * M;
    pw[pk_b16(k, m, M)] = __float2half_rn(w[i]);
}
__global__ void k_packQKV(const float* __restrict__ Wq, const float* __restrict__ Wk,
                          const float* __restrict__ Wv, __half* __restrict__ PW) {
    int i = blockIdx.x * blockDim.x + threadIdx.x;
    const int tot = EE * QKVM;
    if (i >= tot) return;
    int l = blockIdx.y;
    int k = i / QKVM, m = i - k * QKVM;
    float v;
    if (m < EE)          v = Wq[(size_t)l * EE * EE + (size_t)k * EE + m];
    else if (m < 2 * EE) v = Wk[(size_t)l * EE * EE + (size_t)k * EE + (m - EE)];
    else                 v = Wv[(size_t)l * EE * EE + (size_t)k * EE + (m - 2 * EE)];
    PW[(size_t)l * tot + pk_b16(k, m, QKVM)] = __float2half_rn(v);
}
__global__ void k_packWlm(const float* __restrict__ W, __half* __restrict__ PW) {
    int i = blockIdx.x * blockDim.x + threadIdx.x;
    if (i >= EE * 128) return;
    int k = i / 128, m = i - k * 128;
    float v = (m < VV) ? W[(size_t)k * VV + m] : 0.f;
    PW[pk_b16(k, m, 128)] = __float2half_rn(v);
}

// ---------------- embedding --------------------------------------------------
__global__ void k_embed(const int* __restrict__ idx, const float* __restrict__ tok,
                        const float* __restrict__ pos, float* __restrict__ x) {
    int i = blockIdx.x * blockDim.x + threadIdx.x;
    if (i >= NTOK * EE) return;
    int n = i / EE, e = i - n * EE;
    int t = n % TT;
    x[i] = tok[idx[n] * EE + e] + pos[t * EE + e];
}

// ---------------- LayerNorm (fp32 in, packed fp16 out) -----------------------
__global__ void k_ln(const float* __restrict__ x, const float* __restrict__ g,
                     const float* __restrict__ b, __half* __restrict__ y) {
    int warp = threadIdx.x >> 5, lane = threadIdx.x & 31;
    int row = blockIdx.x * 8 + warp;
    if (row >= NTOK) return;
    const float4* xr = (const float4*)(x + (size_t)row * EE);
    float4 v[3];
#pragma unroll
    for (int i = 0; i < 3; i++) v[i] = xr[lane + i * 32];
    float s = 0.f, s2 = 0.f;
#pragma unroll
    for (int i = 0; i < 3; i++) {
        s  += v[i].x + v[i].y + v[i].z + v[i].w;
        s2 += v[i].x * v[i].x + v[i].y * v[i].y + v[i].z * v[i].z + v[i].w * v[i].w;
    }
#pragma unroll
    for (int off = 16; off > 0; off >>= 1) {
        s  += __shfl_xor_sync(0xffffffffu, s,  off);
        s2 += __shfl_xor_sync(0xffffffffu, s2, off);
    }
    float mu = s * (1.f / EE);
    float var = s2 * (1.f / EE) - mu * mu;
    float rs = rsqrtf(var + 1e-5f);
    const float4* gr = (const float4*)g;
    const float4* br = (const float4*)b;
#pragma unroll
    for (int i = 0; i < 3; i++) {
        float4 gg = gr[lane + i * 32], bb = br[lane + i * 32];
        float o0 = (v[i].x - mu) * rs * gg.x + bb.x;
        float o1 = (v[i].y - mu) * rs * gg.y + bb.y;
        float o2 = (v[i].z - mu) * rs * gg.z + bb.z;
        float o3 = (v[i].w - mu) * rs * gg.w + bb.w;
        int cb = (lane + i * 32) * 4;
        *(__half2*)&y[pk_a16(row, cb,     EE)] = __floats2half2_rn(o0, o1);
        *(__half2*)&y[pk_a16(row, cb + 2, EE)] = __floats2half2_rn(o2, o3);
    }
}

// ---------------- persistent fp16 tensor-core GEMM ---------------------------
// C[N,M] = A[N,K] @ W[K,M]; A,W fragment-packed fp16 in global.
// 128x128x32 block tile, 8 warps (2x4), warp tile 64x32, m16n8k16 mma.
// 3-stage cp.async ring (16KB/stage), commit every iter.
// flags: 1=relu, 2=packed fp16 output (Ch), else fp32 natural (Cf).
__global__ void __launch_bounds__(256, 2) k_gemm_h(
    const __half* __restrict__ PA, const __half* __restrict__ PB,
    const float* __restrict__ bias, const float* __restrict__ res,
    float* __restrict__ Cf, __half* __restrict__ Ch,
    int K, int M, int flags, int nTileM, int nTiles)
{
    extern __shared__ __half smh[];
    const int tid  = threadIdx.x;
    const int lane = tid & 31, warp = tid >> 5;
    const int wm = warp & 1, wn = warp >> 1;
    const int gid = lane >> 2, tig = lane & 3;
    const int K16 = K >> 4, M8 = M >> 3;
    const int KB = K >> 5;

    // per-thread channels: 2 A chunks + 2 B chunks (16B each) per stage
    int offA[2], offB[2];
    unsigned sA[2], sB[2];
#pragma unroll
    for (int i = 0; i < 2; i++) {
        int ch = tid + i * 256;                    // [0,512)
        int mt = ch >> 6, kt = (ch >> 5) & 1, ln = ch & 31;
        sA[i]   = (unsigned)(((mt * 2 + kt) * 256 + ln * 8) * 2);
        offA[i] = (mt * K16 + kt) * 256 + ln * 8;
        int bkt = ch >> 8, rem = ch & 255, nt = rem >> 4, c16 = rem & 15;
        sB[i]   = (unsigned)((4096 + (bkt * 16 + nt) * 128 + c16 * 8) * 2);
        offB[i] = (bkt * M8 + nt) * 128 + c16 * 8;
    }
    unsigned smem_u = (unsigned)__cvta_generic_to_shared(smh);
    const bool relu = (flags & 1), pko = (flags & 2);

    for (int t = blockIdx.x; t < nTiles; t += gridDim.x) {
        const int m0 = (t % nTileM) << 7;
        const int n0 = (t / nTileM) << 7;
        const __half* Abase = PA + (size_t)n0 * K;
        const __half* Bbase = PB + (size_t)(m0 >> 3) * 128;

        auto issue = [&](int ks, int buf) {
            unsigned base = smem_u + (unsigned)buf * 16384u;
#pragma unroll
            for (int i = 0; i < 2; i++) cpa16(base + sA[i], Abase + offA[i] + ks * 512);
#pragma unroll
            for (int i = 0; i < 2; i++) cpa16(base + sB[i], Bbase + offB[i] + (size_t)ks * 32 * M);
        };

        float acc[4][4][4];
#pragma unroll
        for (int a = 0; a < 4; a++)
#pragma unroll
            for (int b = 0; b < 4; b++)
#pragma unroll
                for (int c = 0; c < 4; c++) acc[a][b][c] = 0.f;

        issue(0, 0);
        asm volatile("cp.async.commit_group;" ::: "memory");
        issue(1, 1);
        asm volatile("cp.async.commit_group;" ::: "memory");

        int p = 0;
        for (int kb = 0; kb < KB; kb++) {
            asm volatile("cp.async.wait_group 1;" ::: "memory");
            __syncthreads();
            if (kb + 2 < KB) issue(kb + 2, (kb + 2) % 3);
            asm volatile("cp.async.commit_group;" ::: "memory");

            const __half* as = smh + p * 8192;
            const __half* bs = as + 4096;
#pragma unroll
            for (int kt = 0; kt < 2; kt++) {
                unsigned af[4][4], bf[4][2];
#pragma unroll
                for (int mi = 0; mi < 4; mi++) {
                    uint4 v = *(const uint4*)&as[(((wm * 4 + mi) * 2 + kt) * 256) + lane * 8];
                    af[mi][0] = v.x; af[mi][1] = v.y; af[mi][2] = v.z; af[mi][3] = v.w;
                }
#pragma unroll
                for (int ni = 0; ni < 4; ni++) {
                    uint2 v = *(const uint2*)&bs[((kt * 16 + wn * 4 + ni) * 128) + lane * 4];
                    bf[ni][0] = v.x; bf[ni][1] = v.y;
                }
#pragma unroll
                for (int mi = 0; mi < 4; mi++)
#pragma unroll
                    for (int ni = 0; ni < 4; ni++) {
                        asm volatile(
                            "mma.sync.aligned.m16n8k16.row.col.f32.f16.f16.f32 "
                            "{%0,%1,%2,%3}, {%4,%5,%6,%7}, {%8,%9}, {%0,%1,%2,%3};"
                            : "+f"(acc[mi][ni][0]), "+f"(acc[mi][ni][1]),
                              "+f"(acc[mi][ni][2]), "+f"(acc[mi][ni][3])
                            : "r"(af[mi][0]), "r"(af[mi][1]), "r"(af[mi][2]), "r"(af[mi][3]),
                              "r"(bf[ni][0]), "r"(bf[ni][1]));
                    }
            }
            p = (p == 2) ? 0 : p + 1;
        }
        asm volatile("cp.async.wait_group 0;" ::: "memory");

        // epilogue
#pragma unroll
        for (int mi = 0; mi < 4; mi++) {
            int row = n0 + (wm << 6) + (mi << 4) + gid;
#pragma unroll
            for (int ni = 0; ni < 4; ni++) {
                int col = m0 + (wn << 5) + (ni << 3) + (tig << 1);
                float b0 = 0.f, b1 = 0.f;
                if (bias) { b0 = bias[col]; b1 = bias[col + 1]; }
                float v0 = acc[mi][ni][0] + b0;
                float v1 = acc[mi][ni][1] + b1;
                float v2 = acc[mi][ni][2] + b0;
                float v3 = acc[mi][ni][3] + b1;
                if (res) {
                    const float* r0 = res + (size_t)row * M + col;
                    const float* r1 = res + (size_t)(row + 8) * M + col;
                    v0 += r0[0]; v1 += r0[1]; v2 += r1[0]; v3 += r1[1];
                }
                if (relu) {
                    v0 = fmaxf(v0, 0.f); v1 = fmaxf(v1, 0.f);
                    v2 = fmaxf(v2, 0.f); v3 = fmaxf(v3, 0.f);
                }
                if (pko) {
                    *(__half2*)&Ch[pk_a16(row,     col, M)] = __floats2half2_rn(v0, v1);
                    *(__half2*)&Ch[pk_a16(row + 8, col, M)] = __floats2half2_rn(v2, v3);
                } else {
                    *(float2*)(Cf + (size_t)row * M + col)       = make_float2(v0, v1);
                    *(float2*)(Cf + (size_t)(row + 8) * M + col) = make_float2(v2, v3);
                }
            }
        }
        __syncthreads();
    }
}

// ---------------- causal attention (fp32 in, packed fp16 out) ----------------
__global__ void __launch_bounds__(256) k_attn(
    const float* __restrict__ QKV, __half* __restrict__ O)
{
    __shared__ float Ks[64][64];
    __shared__ float Vs[64][64];
    const int hd = blockIdx.x, b = blockIdx.y;
    const int tq = threadIdx.x;
    const float scale = 0.125f;

    float4 q4[16], o4[16];
    const float4* qr = (const float4*)(QKV + (size_t)(b * TT + tq) * QKVM + hd * DD);
#pragma unroll
    for (int i = 0; i < 16; i++) { q4[i] = qr[i]; o4[i] = make_float4(0.f, 0.f, 0.f, 0.f); }
    float m = -INFINITY, l = 0.f;

    for (int c = 0; c < 4; c++) {
#pragma unroll
        for (int i = 0; i < 4; i++) {
            int idx = threadIdx.x + i * 256;
            int r = idx >> 4, d4 = idx & 15;
            size_t goff = (size_t)(b * TT + c * 64 + r) * QKVM + hd * DD;
            ((float4*)&Ks[r][0])[d4] = ((const float4*)(QKV + goff + EE))[d4];
            ((float4*)&Vs[r][0])[d4] = ((const float4*)(QKV + goff + 2 * EE))[d4];
        }
        __syncthreads();
        int rel = tq - c * 64;
        if (rel >= 0) {
            int kend = rel + 1; if (kend > 64) kend = 64;
            int kk = 0;
            for (; kk + 1 < kend; kk += 2) {
                const float4* kr0 = (const float4*)&Ks[kk][0];
                const float4* kr1 = (const float4*)&Ks[kk + 1][0];
                float s0 = 0.f, s1 = 0.f;
#pragma unroll
                for (int i = 0; i < 16; i++) {
                    float4 k0 = kr0[i], k1 = kr1[i], qv = q4[i];
                    s0 += qv.x * k0.x + qv.y * k0.y + qv.z * k0.z + qv.w * k0.w;
                    s1 += qv.x * k1.x + qv.y * k1.y + qv.z * k1.z + qv.w * k1.w;
                }
                s0 *= scale; s1 *= scale;
                float mn = fmaxf(m, fmaxf(s0, s1));
                float al = __expf(m - mn);
                float p0 = __expf(s0 - mn);
                float p1 = __expf(s1 - mn);
                l = l * al + p0 + p1;
                const float4* vr0 = (const float4*)&Vs[kk][0];
                const float4* vr1 = (const float4*)&Vs[kk + 1][0];
#pragma unroll
                for (int i = 0; i < 16; i++) {
                    float4 v0 = vr0[i], v1 = vr1[i];
                    o4[i].x = o4[i].x * al + p0 * v0.x + p1 * v1.x;
                    o4[i].y = o4[i].y * al + p0 * v0.y + p1 * v1.y;
                    o4[i].z = o4[i].z * al + p0 * v0.z + p1 * v1.z;
                    o4[i].w = o4[i].w * al + p0 * v0.w + p1 * v1.w;
                }
                m = mn;
            }
            if (kk < kend) {
                const float4* kr = (const float4*)&Ks[kk][0];
                float s = 0.f;
#pragma unroll
                for (int i = 0; i < 16; i++) {
                    float4 kv = kr[i];
                    s += q4[i].x * kv.x + q4[i].y * kv.y + q4[i].z * kv.z + q4[i].w * kv.w;
                }
                s *= scale;
                float mn = fmaxf(m, s);
                float pp = __expf(s - mn);
                float al = __expf(m - mn);
                l = l * al + pp;
                const float4* vr = (const float4*)&Vs[kk][0];
#pragma unroll
                for (int i = 0; i < 16; i++) {
                    float4 vv = vr[i];
                    o4[i].x = o4[i].x * al + pp * vv.x;
                    o4[i].y = o4[i].y * al + pp * vv.y;
                    o4[i].z = o4[i].z * al + pp * vv.z;
                    o4[i].w = o4[i].w * al + pp * vv.w;
                }
                m = mn;
            }
        }
        __syncthreads();
    }
    float inv = 1.f / l;
    int rowR = b * TT + tq;
#pragma unroll
    for (int i = 0; i < 16; i++) {
        int cb = hd * DD + i * 4;
        *(__half2*)&O[pk_a16(rowR, cb,     EE)] = __floats2half2_rn(o4[i].x * inv, o4[i].y * inv);
        *(__half2*)&O[pk_a16(rowR, cb + 2, EE)] = __floats2half2_rn(o4[i].z * inv, o4[i].w * inv);
    }
}

// ---------------- LM head compact --------------------------------------------
__global__ void k_head_compact(const float* __restrict__ C128,
                               const float* __restrict__ blm,
                               float* __restrict__ logits) {
    int i = blockIdx.x * blockDim.x + threadIdx.x;
    if (i >= NTOK * VV) return;
    int n = i / VV, m = i - n * VV;
    logits[i] = C128[(size_t)n * 128 + m] + blm[m];
}

// ---------------- loss -------------------------------------------------------
__global__ void k_zero(float* loss) { *loss = 0.f; }

__global__ void k_loss(const float* __restrict__ logits, const int* __restrict__ tgt,
                       float* __restrict__ loss) {
    int warp = threadIdx.x >> 5, lane = threadIdx.x & 31;
    int row = blockIdx.x * 8 + warp;
    if (row >= NTOK) return;
    const float* lr = logits + (size_t)row * VV;
    float x0 = (lane < VV)      ? lr[lane]      : -INFINITY;
    float x1 = (lane + 32 < VV) ? lr[lane + 32] : -INFINITY;
    float x2 = (lane + 64 < VV) ? lr[lane + 64] : -INFINITY;
    float mx = fmaxf(x0, fmaxf(x1, x2));
#pragma unroll
    for (int off = 16; off > 0; off >>= 1) mx = fmaxf(mx, __shfl_xor_sync(0xffffffffu, mx, off));
    float se = 0.f;
    if (lane < VV)      se += expf(x0 - mx);
    if (lane + 32 < VV) se += expf(x1 - mx);
    if (lane + 64 < VV) se += expf(x2 - mx);
#pragma unroll
    for (int off = 16; off > 0; off >>= 1) se += __shfl_xor_sync(0xffffffffu, se, off);
    if (lane == 0) {
        float lt = lr[tgt[row]];
        atomicAdd(loss, mx + logf(se) - lt);
    }
}

__global__ void k_final(const float* __restrict__ loss, float* __restrict__ out) {
    out[0] = *loss * (1.f / NTOK);
}

// ---------------- host -------------------------------------------------------
extern "C" void kernel_launch(void* const* d_in, const int* in_sizes, int n_in,
                              void* d_out, int out_size) {
    const int*   idx  = (const int*)  d_in[0];
    const int*   tgt  = (const int*)  d_in[1];
    const float* tok  = (const float*)d_in[2];
    const float* pos  = (const float*)d_in[3];
    const float* Wq   = (const float*)d_in[4];
    const float* Wk   = (const float*)d_in[5];
    const float* Wv   = (const float*)d_in[6];
    const float* Wo   = (const float*)d_in[7];
    const float* bo   = (const float*)d_in[8];
    const float* W1   = (const float*)d_in[9];
    const float* b1   = (const float*)d_in[10];
    const float* W2   = (const float*)d_in[11];
    const float* b2w  = (const float*)d_in[12];
    const float* ln1g = (const float*)d_in[13];
    const float* ln1b = (const float*)d_in[14];
    const float* ln2g = (const float*)d_in[15];
    const float* ln2b = (const float*)d_in[16];
    const float* lnfg = (const float*)d_in[17];
    const float* lnfb = (const float*)d_in[18];
    const float* Wlm  = (const float*)d_in[19];
    const float* blm  = (const float*)d_in[20];

    float *x, *qkv, *hd, *glog, *gloss;
    __half *h16, *att16, *f16, *pw;
    cudaGetSymbolAddress((void**)&x,     g_x);
    cudaGetSymbolAddress((void**)&h16,   g_h16);
    cudaGetSymbolAddress((void**)&qkv,   g_qkv);
    cudaGetSymbolAddress((void**)&att16, g_att16);
    cudaGetSymbolAddress((void**)&f16,   g_f16);
    cudaGetSymbolAddress((void**)&hd,    g_hd);
    cudaGetSymbolAddress((void**)&glog,  g_logits);
    cudaGetSymbolAddress((void**)&gloss, g_loss);
    cudaGetSymbolAddress((void**)&pw,    g_pw16);

    static int smem_set = 0;
    const int DSM = 49152;   // 3 stages x 16KB
    if (!smem_set) {
        cudaFuncSetAttribute(k_gemm_h, cudaFuncAttributeMaxDynamicSharedMemorySize, DSM);
        smem_set = 1;
    }

    const size_t EExEE = (size_t)EE * EE, EExFF = (size_t)EE * FF, EExQ = (size_t)EE * QKVM;
    __half* pqkv = pw;
    __half* pwo  = pqkv + (size_t)LLAY * EExQ;
    __half* pw1  = pwo  + (size_t)LLAY * EExEE;
    __half* pw2  = pw1  + (size_t)LLAY * EExFF;
    __half* pwlm = pw2  + (size_t)LLAY * EExFF;

    k_packQKV<<<dim3((EE * QKVM + 255) / 256, LLAY), 256>>>(Wq, Wk, Wv, pqkv);
    k_packW<<<dim3((EE * EE + 255) / 256, LLAY), 256>>>(Wo, pwo, EE, EE);
    k_packW<<<dim3((EE * FF + 255) / 256, LLAY), 256>>>(W1, pw1, EE, FF);
    k_packW<<<dim3((EE * FF + 255) / 256, LLAY), 256>>>(W2, pw2, FF, EE);
    k_packWlm<<<(EE * 128 + 255) / 256, 256>>>(Wlm, pwlm);

    float* outf   = (float*)d_out;
    float* logits = (out_size >= NTOK * VV) ? outf : glog;

    k_embed<<<(NTOK * EE + 255) / 256, 256>>>(idx, tok, pos, x);

    const int nRow = NTOK / 128;              // 128
    const int tQ = (QKVM / 128) * nRow;       // 1152
    const int tE = (EE / 128) * nRow;         // 384
    const int tF = (FF / 128) * nRow;         // 1536
    dim3 gLN(NTOK / 8);

    for (int l = 0; l < LLAY; l++) {
        k_ln<<<gLN, 256>>>(x, ln1g + l * EE, ln1b + l * EE, h16);
        k_gemm_h<<<GEMM_GRID, 256, DSM>>>(h16, pqkv + (size_t)l * EExQ, nullptr, nullptr,
                                          qkv, nullptr, EE, QKVM, 0, QKVM / 128, tQ);
        k_attn<<<dim3(HH, BB), 256>>>(qkv, att16);
        k_gemm_h<<<GEMM_GRID, 256, DSM>>>(att16, pwo + (size_t)l * EExEE, bo + l * EE, x,
                                          x, nullptr, EE, EE, 0, EE / 128, tE);
        k_ln<<<gLN, 256>>>(x, ln2g + l * EE, ln2b + l * EE, h16);
        k_gemm_h<<<GEMM_GRID, 256, DSM>>>(h16, pw1 + (size_t)l * EExFF, b1 + l * FF, nullptr,
                                          nullptr, f16, EE, FF, 1 | 2, FF / 128, tF);
        k_gemm_h<<<GEMM_GRID, 256, DSM>>>(f16, pw2 + (size_t)l * EExFF, b2w + l * EE, x,
                                          x, nullptr, FF, EE, 0, EE / 128, tE);
    }

    k_ln<<<gLN, 256>>>(x, lnfg, lnfb, h16);
    k_gemm_h<<<GEMM_GRID, 256, DSM>>>(h16, pwlm, nullptr, nullptr,
                                      hd, nullptr, EE, 128, 0, 1, nRow);
    k_head_compact<<<(NTOK * VV + 255) / 256, 256>>>(hd, blm, logits);

    if (out_size == 1 || out_size > NTOK * VV) {
        k_zero<<<1, 1>>>(gloss);
        k_loss<<<NTOK / 8, 256>>>(logits, tgt, gloss);
        float* ldst = (out_size == 1) ? outf : (outf + NTOK * VV);
        k_final<<<1, 1>>>(gloss, ldst);
    }
}

// round 14
// speedup vs baseline: 1.3586x; 1.0082x over previous
#include <cuda_runtime.h>
#include <cuda_fp16.h>
#include <math.h>

// Problem constants
static const int BB = 64, TT = 256, VV = 65, EE = 384, HH = 6, LLAY = 6, DD = 64, FF = 1536;
static const int NTOK = BB * TT; // 16384
static const int QKVM = 3 * EE;  // 1152
static const int GEMM_GRID = 296;

// ---------------- scratch ----------------------------------------------------
__device__ __align__(16) float  g_x   [16384 * 384];
__device__ __align__(16) __half g_h16 [16384 * 384];    // packed LN output
__device__ __align__(16) float  g_qkv [16384 * 1152];   // natural fp32
__device__ __align__(16) __half g_att16[16384 * 384];   // packed
__device__ __align__(16) __half g_f16 [16384 * 1536];   // packed FFN mid
__device__ __align__(16) float  g_hd  [16384 * 128];    // head GEMM out
__device__ __align__(16) float  g_logits[16384 * 65];
__device__ __align__(16) float  g_loss[1];
__device__ __align__(16) __half g_pw16[10665984];

// ---------------- fp16 m16n8k16 fragment-packed indices ----------------------
__device__ __forceinline__ size_t pk_a16(int row, int col, int K) {
    return ((size_t)(row >> 4) * (K >> 4) + (col >> 4)) * 256
         + ((row & 7) * 4 + ((col & 7) >> 1)) * 8
         + (((col >> 3) & 1) * 2 + ((row >> 3) & 1)) * 2 + (col & 1);
}
__device__ __forceinline__ size_t pk_b16(int k, int m, int M) {
    return ((size_t)(k >> 4) * (M >> 3) + (m >> 3)) * 128
         + ((m & 7) * 4 + ((k & 7) >> 1)) * 4
         + ((k >> 3) & 1) * 2 + (k & 1);
}
__device__ __forceinline__ void cpa16(unsigned s, const void* g) {
    asm volatile("cp.async.cg.shared.global [%0], [%1], 16;" :: "r"(s), "l"(g));
}

// ---------------- weight pre-pack --------------------------------------------
__global__ void k_packW(const float* __restrict__ W, __half* __restrict__ PW,
                        int K, int M) {
    int i = blockIdx.x * blockDim.x + threadIdx.x;
    int tot = K * M;
    if (i >= tot) return;
    const float* w = W + (size_t)blockIdx.y * tot;
    __half* pw = PW + (size_t)blockIdx.y * tot;
    int k = i / M, m = i - k * M;
    pw[pk_b16(k, m, M)] = __float2half_rn(w[i]);
}
__global__ void k_packQKV(const float* __restrict__ Wq, const float* __restrict__ Wk,
                          const float* __restrict__ Wv, __half* __restrict__ PW) {
    int i = blockIdx.x * blockDim.x + threadIdx.x;
    const int tot = EE * QKVM;
    if (i >= tot) return;
    int l = blockIdx.y;
    int k = i / QKVM, m = i - k * QKVM;
    float v;
    if (m < EE)          v = Wq[(size_t)l * EE * EE + (size_t)k * EE + m];
    else if (m < 2 * EE) v = Wk[(size_t)l * EE * EE + (size_t)k * EE + (m - EE)];
    else                 v = Wv[(size_t)l * EE * EE + (size_t)k * EE + (m - 2 * EE)];
    PW[(size_t)l * tot + pk_b16(k, m, QKVM)] = __float2half_rn(v);
}
__global__ void k_packWlm(const float* __restrict__ W, __half* __restrict__ PW) {
    int i = blockIdx.x * blockDim.x + threadIdx.x;
    if (i >= EE * 128) return;
    int k = i / 128, m = i - k * 128;
    float v = (m < VV) ? W[(size_t)k * VV + m] : 0.f;
    PW[pk_b16(k, m, 128)] = __float2half_rn(v);
}

// ---------------- embedding --------------------------------------------------
__global__ void k_embed(const int* __restrict__ idx, const float* __restrict__ tok,
                        const float* __restrict__ pos, float* __restrict__ x) {
    int i = blockIdx.x * blockDim.x + threadIdx.x;
    if (i >= NTOK * EE) return;
    int n = i / EE, e = i - n * EE;
    int t = n % TT;
    x[i] = tok[idx[n] * EE + e] + pos[t * EE + e];
}

// ---------------- LayerNorm (fp32 in, packed fp16 out) -----------------------
__global__ void k_ln(const float* __restrict__ x, const float* __restrict__ g,
                     const float* __restrict__ b, __half* __restrict__ y) {
    int warp = threadIdx.x >> 5, lane = threadIdx.x & 31;
    int row = blockIdx.x * 8 + warp;
    if (row >= NTOK) return;
    const float4* xr = (const float4*)(x + (size_t)row * EE);
    float4 v[3];
#pragma unroll
    for (int i = 0; i < 3; i++) v[i] = xr[lane + i * 32];
    float s = 0.f, s2 = 0.f;
#pragma unroll
    for (int i = 0; i < 3; i++) {
        s  += v[i].x + v[i].y + v[i].z + v[i].w;
        s2 += v[i].x * v[i].x + v[i].y * v[i].y + v[i].z * v[i].z + v[i].w * v[i].w;
    }
#pragma unroll
    for (int off = 16; off > 0; off >>= 1) {
        s  += __shfl_xor_sync(0xffffffffu, s,  off);
        s2 += __shfl_xor_sync(0xffffffffu, s2, off);
    }
    float mu = s * (1.f / EE);
    float var = s2 * (1.f / EE) - mu * mu;
    float rs = rsqrtf(var + 1e-5f);
    const float4* gr = (const float4*)g;
    const float4* br = (const float4*)b;
#pragma unroll
    for (int i = 0; i < 3; i++) {
        float4 gg = gr[lane + i * 32], bb = br[lane + i * 32];
        float o0 = (v[i].x - mu) * rs * gg.x + bb.x;
        float o1 = (v[i].y - mu) * rs * gg.y + bb.y;
        float o2 = (v[i].z - mu) * rs * gg.z + bb.z;
        float o3 = (v[i].w - mu) * rs * gg.w + bb.w;
        int cb = (lane + i * 32) * 4;
        *(__half2*)&y[pk_a16(row, cb,     EE)] = __floats2half2_rn(o0, o1);
        *(__half2*)&y[pk_a16(row, cb + 2, EE)] = __floats2half2_rn(o2, o3);
    }
}

// ---------------- persistent fp16 tensor-core GEMM (64-K slabs) --------------
// C[N,M] = A[N,K] @ W[K,M]; A,W fragment-packed fp16 in global.
// 128x128x64 slab tile, 8 warps (2x4), warp tile 64x32, m16n8k16 mma.
// 3-stage cp.async ring (32KB/stage), commit every iter.
// flags: 1=relu, 2=packed fp16 output (Ch), else fp32 natural (Cf).
__global__ void __launch_bounds__(256, 2) k_gemm_h(
    const __half* __restrict__ PA, const __half* __restrict__ PB,
    const float* __restrict__ bias, const float* __restrict__ res,
    float* __restrict__ Cf, __half* __restrict__ Ch,
    int K, int M, int flags, int nTileM, int nTiles)
{
    extern __shared__ __half smh[];
    const int tid  = threadIdx.x;
    const int lane = tid & 31, warp = tid >> 5;
    const int wm = warp & 1, wn = warp >> 1;
    const int gid = lane >> 2, tig = lane & 3;
    const int K16 = K >> 4, M8 = M >> 3;
    const int KB = K >> 6;                 // 64-K slabs

    // per-thread channels: 4 A chunks + 4 B chunks (16B each) per stage
    int offA[4], offB[4];
    unsigned sA[4], sB[4];
#pragma unroll
    for (int i = 0; i < 4; i++) {
        int ch = tid + i * 256;                    // [0,1024)
        int mt = ch >> 7, kt = (ch >> 5) & 3, ln = ch & 31;
        sA[i]   = (unsigned)(((mt * 4 + kt) * 256 + ln * 8) * 2);
        offA[i] = (mt * K16 + kt) * 256 + ln * 8;
        int bkt = ch >> 8, rem = ch & 255, nt = rem >> 4, c16 = rem & 15;
        sB[i]   = (unsigned)((8192 + (bkt * 16 + nt) * 128 + c16 * 8) * 2);
        offB[i] = (bkt * M8 + nt) * 128 + c16 * 8;
    }
    unsigned smem_u = (unsigned)__cvta_generic_to_shared(smh);
    const bool relu = (flags & 1), pko = (flags & 2);

    for (int t = blockIdx.x; t < nTiles; t += gridDim.x) {
        const int m0 = (t % nTileM) << 7;
        const int n0 = (t / nTileM) << 7;
        const __half* Abase = PA + (size_t)n0 * K;
        const __half* Bbase = PB + (size_t)(m0 >> 3) * 128;

        auto issue = [&](int ks, int buf) {
            unsigned base = smem_u + (unsigned)buf * 32768u;
#pragma unroll
            for (int i = 0; i < 4; i++) cpa16(base + sA[i], Abase + offA[i] + ks * 1024);
#pragma unroll
            for (int i = 0; i < 4; i++) cpa16(base + sB[i], Bbase + offB[i] + (size_t)ks * 64 * M);
        };

        float acc[4][4][4];
#pragma unroll
        for (int a = 0; a < 4; a++)
#pragma unroll
            for (int b = 0; b < 4; b++)
#pragma unroll
                for (int c = 0; c < 4; c++) acc[a][b][c] = 0.f;

        issue(0, 0);
        asm volatile("cp.async.commit_group;" ::: "memory");
        if (KB > 1) issue(1, 1);
        asm volatile("cp.async.commit_group;" ::: "memory");

        int p = 0;
        for (int kb = 0; kb < KB; kb++) {
            asm volatile("cp.async.wait_group 1;" ::: "memory");
            __syncthreads();
            if (kb + 2 < KB) issue(kb + 2, (kb + 2) % 3);
            asm volatile("cp.async.commit_group;" ::: "memory");

            const __half* as = smh + (size_t)p * 16384;
            const __half* bs = as + 8192;
#pragma unroll
            for (int kt = 0; kt < 4; kt++) {
                unsigned af[4][4], bf[4][2];
#pragma unroll
                for (int mi = 0; mi < 4; mi++) {
                    uint4 v = *(const uint4*)&as[(((wm * 4 + mi) * 4 + kt) * 256) + lane * 8];
                    af[mi][0] = v.x; af[mi][1] = v.y; af[mi][2] = v.z; af[mi][3] = v.w;
                }
#pragma unroll
                for (int ni = 0; ni < 4; ni++) {
                    uint2 v = *(const uint2*)&bs[((kt * 16 + wn * 4 + ni) * 128) + lane * 4];
                    bf[ni][0] = v.x; bf[ni][1] = v.y;
                }
#pragma unroll
                for (int mi = 0; mi < 4; mi++)
#pragma unroll
                    for (int ni = 0; ni < 4; ni++) {
                        asm volatile(
                            "mma.sync.aligned.m16n8k16.row.col.f32.f16.f16.f32 "
                            "{%0,%1,%2,%3}, {%4,%5,%6,%7}, {%8,%9}, {%0,%1,%2,%3};"
                            : "+f"(acc[mi][ni][0]), "+f"(acc[mi][ni][1]),
                              "+f"(acc[mi][ni][2]), "+f"(acc[mi][ni][3])
                            : "r"(af[mi][0]), "r"(af[mi][1]), "r"(af[mi][2]), "r"(af[mi][3]),
                              "r"(bf[ni][0]), "r"(bf[ni][1]));
                    }
            }
            p = (p == 2) ? 0 : p + 1;
        }
        asm volatile("cp.async.wait_group 0;" ::: "memory");

        // epilogue
#pragma unroll
        for (int mi = 0; mi < 4; mi++) {
            int row = n0 + (wm << 6) + (mi << 4) + gid;
#pragma unroll
            for (int ni = 0; ni < 4; ni++) {
                int col = m0 + (wn << 5) + (ni << 3) + (tig << 1);
                float b0 = 0.f, b1 = 0.f;
                if (bias) { b0 = bias[col]; b1 = bias[col + 1]; }
                float v0 = acc[mi][ni][0] + b0;
                float v1 = acc[mi][ni][1] + b1;
                float v2 = acc[mi][ni][2] + b0;
                float v3 = acc[mi][ni][3] + b1;
                if (res) {
                    const float* r0 = res + (size_t)row * M + col;
                    const float* r1 = res + (size_t)(row + 8) * M + col;
                    v0 += r0[0]; v1 += r0[1]; v2 += r1[0]; v3 += r1[1];
                }
                if (relu) {
                    v0 = fmaxf(v0, 0.f); v1 = fmaxf(v1, 0.f);
                    v2 = fmaxf(v2, 0.f); v3 = fmaxf(v3, 0.f);
                }
                if (pko) {
                    *(__half2*)&Ch[pk_a16(row,     col, M)] = __floats2half2_rn(v0, v1);
                    *(__half2*)&Ch[pk_a16(row + 8, col, M)] = __floats2half2_rn(v2, v3);
                } else {
                    *(float2*)(Cf + (size_t)row * M + col)       = make_float2(v0, v1);
                    *(float2*)(Cf + (size_t)(row + 8) * M + col) = make_float2(v2, v3);
                }
            }
        }
        __syncthreads();
    }
}

// ---------------- causal attention (fp32 in, packed fp16 out) ----------------
// SMSP-balanced warp->query-block map: sigma pairs complementary workloads on
// each scheduler (wid%4): {0,4}->blk{0,7}, {1,5}->blk{1,6}, etc.
__global__ void __launch_bounds__(256) k_attn(
    const float* __restrict__ QKV, __half* __restrict__ O)
{
    __shared__ float Ks[64][64];
    __shared__ float Vs[64][64];
    const int hd = blockIdx.x, b = blockIdx.y;
    const int warp = threadIdx.x >> 5, lane = threadIdx.x & 31;
    const int sigma[8] = {0, 1, 2, 3, 7, 6, 5, 4};
    const int tq = sigma[warp] * 32 + lane;
    const float scale = 0.125f;

    float4 q4[16], o4[16];
    const float4* qr = (const float4*)(QKV + (size_t)(b * TT + tq) * QKVM + hd * DD);
#pragma unroll
    for (int i = 0; i < 16; i++) { q4[i] = qr[i]; o4[i] = make_float4(0.f, 0.f, 0.f, 0.f); }
    float m = -INFINITY, l = 0.f;

    for (int c = 0; c < 4; c++) {
#pragma unroll
        for (int i = 0; i < 4; i++) {
            int idx = threadIdx.x + i * 256;
            int r = idx >> 4, d4 = idx & 15;
            size_t goff = (size_t)(b * TT + c * 64 + r) * QKVM + hd * DD;
            ((float4*)&Ks[r][0])[d4] = ((const float4*)(QKV + goff + EE))[d4];
            ((float4*)&Vs[r][0])[d4] = ((const float4*)(QKV + goff + 2 * EE))[d4];
        }
        __syncthreads();
        int rel = tq - c * 64;
        if (rel >= 0) {
            int kend = rel + 1; if (kend > 64) kend = 64;
            int kk = 0;
            for (; kk + 1 < kend; kk += 2) {
                const float4* kr0 = (const float4*)&Ks[kk][0];
                const float4* kr1 = (const float4*)&Ks[kk + 1][0];
                float s0 = 0.f, s1 = 0.f;
#pragma unroll
                for (int i = 0; i < 16; i++) {
                    float4 k0 = kr0[i], k1 = kr1[i], qv = q4[i];
                    s0 += qv.x * k0.x + qv.y * k0.y + qv.z * k0.z + qv.w * k0.w;
                    s1 += qv.x * k1.x + qv.y * k1.y + qv.z * k1.z + qv.w * k1.w;
                }
                s0 *= scale; s1 *= scale;
                float mn = fmaxf(m, fmaxf(s0, s1));
                float al = __expf(m - mn);
                float p0 = __expf(s0 - mn);
                float p1 = __expf(s1 - mn);
                l = l * al + p0 + p1;
                const float4* vr0 = (const float4*)&Vs[kk][0];
                const float4* vr1 = (const float4*)&Vs[kk + 1][0];
#pragma unroll
                for (int i = 0; i < 16; i++) {
                    float4 v0 = vr0[i], v1 = vr1[i];
                    o4[i].x = o4[i].x * al + p0 * v0.x + p1 * v1.x;
                    o4[i].y = o4[i].y * al + p0 * v0.y + p1 * v1.y;
                    o4[i].z = o4[i].z * al + p0 * v0.z + p1 * v1.z;
                    o4[i].w = o4[i].w * al + p0 * v0.w + p1 * v1.w;
                }
                m = mn;
            }
            if (kk < kend) {
                const float4* kr = (const float4*)&Ks[kk][0];
                float s = 0.f;
#pragma unroll
                for (int i = 0; i < 16; i++) {
                    float4 kv = kr[i];
                    s += q4[i].x * kv.x + q4[i].y * kv.y + q4[i].z * kv.z + q4[i].w * kv.w;
                }
                s *= scale;
                float mn = fmaxf(m, s);
                float pp = __expf(s - mn);
                float al = __expf(m - mn);
                l = l * al + pp;
                const float4* vr = (const float4*)&Vs[kk][0];
#pragma unroll
                for (int i = 0; i < 16; i++) {
                    float4 vv = vr[i];
                    o4[i].x = o4[i].x * al + pp * vv.x;
                    o4[i].y = o4[i].y * al + pp * vv.y;
                    o4[i].z = o4[i].z * al + pp * vv.z;
                    o4[i].w = o4[i].w * al + pp * vv.w;
                }
                m = mn;
            }
        }
        __syncthreads();
    }
    float inv = 1.f / l;
    int rowR = b * TT + tq;
#pragma unroll
    for (int i = 0; i < 16; i++) {
        int cb = hd * DD + i * 4;
        *(__half2*)&O[pk_a16(rowR, cb,     EE)] = __floats2half2_rn(o4[i].x * inv, o4[i].y * inv);
        *(__half2*)&O[pk_a16(rowR, cb + 2, EE)] = __floats2half2_rn(o4[i].z * inv, o4[i].w * inv);
    }
}

// ---------------- LM head compact --------------------------------------------
__global__ void k_head_compact(const float* __restrict__ C128,
                               const float* __restrict__ blm,
                               float* __restrict__ logits) {
    int i = blockIdx.x * blockDim.x + threadIdx.x;
    if (i >= NTOK * VV) return;
    int n = i / VV, m = i - n * VV;
    logits[i] = C128[(size_t)n * 128 + m] + blm[m];
}

// ---------------- loss -------------------------------------------------------
__global__ void k_zero(float* loss) { *loss = 0.f; }

__global__ void k_loss(const float* __restrict__ logits, const int* __restrict__ tgt,
                       float* __restrict__ loss) {
    int warp = threadIdx.x >> 5, lane = threadIdx.x & 31;
    int row = blockIdx.x * 8 + warp;
    if (row >= NTOK) return;
    const float* lr = logits + (size_t)row * VV;
    float x0 = (lane < VV)      ? lr[lane]      : -INFINITY;
    float x1 = (lane + 32 < VV) ? lr[lane + 32] : -INFINITY;
    float x2 = (lane + 64 < VV) ? lr[lane + 64] : -INFINITY;
    float mx = fmaxf(x0, fmaxf(x1, x2));
#pragma unroll
    for (int off = 16; off > 0; off >>= 1) mx = fmaxf(mx, __shfl_xor_sync(0xffffffffu, mx, off));
    float se = 0.f;
    if (lane < VV)      se += expf(x0 - mx);
    if (lane + 32 < VV) se += expf(x1 - mx);
    if (lane + 64 < VV) se += expf(x2 - mx);
#pragma unroll
    for (int off = 16; off > 0; off >>= 1) se += __shfl_xor_sync(0xffffffffu, se, off);
    if (lane == 0) {
        float lt = lr[tgt[row]];
        atomicAdd(loss, mx + logf(se) - lt);
    }
}

__global__ void k_final(const float* __restrict__ loss, float* __restrict__ out) {
    out[0] = *loss * (1.f / NTOK);
}

// ---------------- host -------------------------------------------------------
extern "C" void kernel_launch(void* const* d_in, const int* in_sizes, int n_in,
                              void* d_out, int out_size) {
    const int*   idx  = (const int*)  d_in[0];
    const int*   tgt  = (const int*)  d_in[1];
    const float* tok  = (const float*)d_in[2];
    const float* pos  = (const float*)d_in[3];
    const float* Wq   = (const float*)d_in[4];
    const float* Wk   = (const float*)d_in[5];
    const float* Wv   = (const float*)d_in[6];
    const float* Wo   = (const float*)d_in[7];
    const float* bo   = (const float*)d_in[8];
    const float* W1   = (const float*)d_in[9];
    const float* b1   = (const float*)d_in[10];
    const float* W2   = (const float*)d_in[11];
    const float* b2w  = (const float*)d_in[12];
    const float* ln1g = (const float*)d_in[13];
    const float* ln1b = (const float*)d_in[14];
    const float* ln2g = (const float*)d_in[15];
    const float* ln2b = (const float*)d_in[16];
    const float* lnfg = (const float*)d_in[17];
    const float* lnfb = (const float*)d_in[18];
    const float* Wlm  = (const float*)d_in[19];
    const float* blm  = (const float*)d_in[20];

    float *x, *qkv, *hd, *glog, *gloss;
    __half *h16, *att16, *f16, *pw;
    cudaGetSymbolAddress((void**)&x,     g_x);
    cudaGetSymbolAddress((void**)&h16,   g_h16);
    cudaGetSymbolAddress((void**)&qkv,   g_qkv);
    cudaGetSymbolAddress((void**)&att16, g_att16);
    cudaGetSymbolAddress((void**)&f16,   g_f16);
    cudaGetSymbolAddress((void**)&hd,    g_hd);
    cudaGetSymbolAddress((void**)&glog,  g_logits);
    cudaGetSymbolAddress((void**)&gloss, g_loss);
    cudaGetSymbolAddress((void**)&pw,    g_pw16);

    static int smem_set = 0;
    const int DSM = 98304;   // 3 stages x 32KB
    if (!smem_set) {
        cudaFuncSetAttribute(k_gemm_h, cudaFuncAttributeMaxDynamicSharedMemorySize, DSM);
        smem_set = 1;
    }

    const size_t EExEE = (size_t)EE * EE, EExFF = (size_t)EE * FF, EExQ = (size_t)EE * QKVM;
    __half* pqkv = pw;
    __half* pwo  = pqkv + (size_t)LLAY * EExQ;
    __half* pw1  = pwo  + (size_t)LLAY * EExEE;
    __half* pw2  = pw1  + (size_t)LLAY * EExFF;
    __half* pwlm = pw2  + (size_t)LLAY * EExFF;

    k_packQKV<<<dim3((EE * QKVM + 255) / 256, LLAY), 256>>>(Wq, Wk, Wv, pqkv);
    k_packW<<<dim3((EE * EE + 255) / 256, LLAY), 256>>>(Wo, pwo, EE, EE);
    k_packW<<<dim3((EE * FF + 255) / 256, LLAY), 256>>>(W1, pw1, EE, FF);
    k_packW<<<dim3((EE * FF + 255) / 256, LLAY), 256>>>(W2, pw2, FF, EE);
    k_packWlm<<<(EE * 128 + 255) / 256, 256>>>(Wlm, pwlm);

    float* outf   = (float*)d_out;
    float* logits = (out_size >= NTOK * VV) ? outf : glog;

    k_embed<<<(NTOK * EE + 255) / 256, 256>>>(idx, tok, pos, x);

    const int nRow = NTOK / 128;              // 128
    const int tQ = (QKVM / 128) * nRow;       // 1152
    const int tE = (EE / 128) * nRow;         // 384
    const int tF = (FF / 128) * nRow;         // 1536
    dim3 gLN(NTOK / 8);

    for (int l = 0; l < LLAY; l++) {
        k_ln<<<gLN, 256>>>(x, ln1g + l * EE, ln1b + l * EE, h16);
        k_gemm_h<<<GEMM_GRID, 256, DSM>>>(h16, pqkv + (size_t)l * EExQ, nullptr, nullptr,
                                          qkv, nullptr, EE, QKVM, 0, QKVM / 128, tQ);
        k_attn<<<dim3(HH, BB), 256>>>(qkv, att16);
        k_gemm_h<<<GEMM_GRID, 256, DSM>>>(att16, pwo + (size_t)l * EExEE, bo + l * EE, x,
                                          x, nullptr, EE, EE, 0, EE / 128, tE);
        k_ln<<<gLN, 256>>>(x, ln2g + l * EE, ln2b + l * EE, h16);
        k_gemm_h<<<GEMM_GRID, 256, DSM>>>(h16, pw1 + (size_t)l * EExFF, b1 + l * FF, nullptr,
                                          nullptr, f16, EE, FF, 1 | 2, FF / 128, tF);
        k_gemm_h<<<GEMM_GRID, 256, DSM>>>(f16, pw2 + (size_t)l * EExFF, b2w + l * EE, x,
                                          x, nullptr, FF, EE, 0, EE / 128, tE);
    }

    k_ln<<<gLN, 256>>>(x, lnfg, lnfb, h16);
    k_gemm_h<<<GEMM_GRID, 256, DSM>>>(h16, pwlm, nullptr, nullptr,
                                      hd, nullptr, EE, 128, 0, 1, nRow);
    k_head_compact<<<(NTOK * VV + 255) / 256, 256>>>(hd, blm, logits);

    if (out_size == 1 || out_size > NTOK * VV) {
        k_zero<<<1, 1>>>(gloss);
        k_loss<<<NTOK / 8, 256>>>(logits, tgt, gloss);
        float* ldst = (out_size == 1) ? outf : (outf + NTOK * VV);
        k_final<<<1, 1>>>(gloss, ldst);
    }
}

// round 16
// speedup vs baseline: 2.2680x; 1.6693x over previous
#include <cuda_runtime.h>
#include <cuda_fp16.h>
#include <math.h>

// Problem constants
static const int BB = 64, TT = 256, VV = 65, EE = 384, HH = 6, LLAY = 6, DD = 64, FF = 1536;
static const int NTOK = BB * TT; // 16384
static const int QKVM = 3 * EE;  // 1152
static const int GEMM_GRID = 296;

// ---------------- scratch ----------------------------------------------------
__device__ __align__(16) float  g_x   [16384 * 384];
__device__ __align__(16) __half g_h16 [16384 * 384];    // packed LN output
__device__ __align__(16) __half g_qkv [16384 * 1152];   // natural fp16, stride 1152
__device__ __align__(16) __half g_att16[16384 * 384];   // packed
__device__ __align__(16) __half g_f16 [16384 * 1536];   // packed FFN mid
__device__ __align__(16) float  g_hd  [16384 * 128];    // head GEMM out
__device__ __align__(16) float  g_logits[16384 * 65];
__device__ __align__(16) float  g_loss[1];
__device__ __align__(16) __half g_pw16[10665984];

// ---------------- fp16 m16n8k16 fragment-packed indices ----------------------
__device__ __forceinline__ size_t pk_a16(int row, int col, int K) {
    return ((size_t)(row >> 4) * (K >> 4) + (col >> 4)) * 256
         + ((row & 7) * 4 + ((col & 7) >> 1)) * 8
         + (((col >> 3) & 1) * 2 + ((row >> 3) & 1)) * 2 + (col & 1);
}
__device__ __forceinline__ size_t pk_b16(int k, int m, int M) {
    return ((size_t)(k >> 4) * (M >> 3) + (m >> 3)) * 128
         + ((m & 7) * 4 + ((k & 7) >> 1)) * 4
         + ((k >> 3) & 1) * 2 + (k & 1);
}
__device__ __forceinline__ void cpa16(unsigned s, const void* g) {
    asm volatile("cp.async.cg.shared.global [%0], [%1], 16;" :: "r"(s), "l"(g));
}
#define MMA_F16(acc, a, b) \
    asm volatile("mma.sync.aligned.m16n8k16.row.col.f32.f16.f16.f32 " \
        "{%0,%1,%2,%3}, {%4,%5,%6,%7}, {%8,%9}, {%0,%1,%2,%3};" \
        : "+f"((acc)[0]), "+f"((acc)[1]), "+f"((acc)[2]), "+f"((acc)[3]) \
        : "r"((a)[0]), "r"((a)[1]), "r"((a)[2]), "r"((a)[3]), \
          "r"((b)[0]), "r"((b)[1]))

// ---------------- weight pre-pack --------------------------------------------
__global__ void k_packW(const float* __restrict__ W, __half* __restrict__ PW,
                        int K, int M) {
    int i = blockIdx.x * blockDim.x + threadIdx.x;
    int tot = K * M;
    if (i >= tot) return;
    const float* w = W + (size_t)blockIdx.y * tot;
    __half* pw = PW + (size_t)blockIdx.y * tot;
    int k = i / M, m = i - k * M;
    pw[pk_b16(k, m, M)] = __float2half_rn(w[i]);
}
__global__ void k_packQKV(const float* __restrict__ Wq, const float* __restrict__ Wk,
                          const float* __restrict__ Wv, __half* __restrict__ PW) {
    int i = blockIdx.x * blockDim.x + threadIdx.x;
    const int tot = EE * QKVM;
    if (i >= tot) return;
    int l = blockIdx.y;
    int k = i / QKVM, m = i - k * QKVM;
    float v;
    if (m < EE)          v = Wq[(size_t)l * EE * EE + (size_t)k * EE + m];
    else if (m < 2 * EE) v = Wk[(size_t)l * EE * EE + (size_t)k * EE + (m - EE)];
    else                 v = Wv[(size_t)l * EE * EE + (size_t)k * EE + (m - 2 * EE)];
    PW[(size_t)l * tot + pk_b16(k, m, QKVM)] = __float2half_rn(v);
}
__global__ void k_packWlm(const float* __restrict__ W, __half* __restrict__ PW) {
    int i = blockIdx.x * blockDim.x + threadIdx.x;
    if (i >= EE * 128) return;
    int k = i / 128, m = i - k * 128;
    float v = (m < VV) ? W[(size_t)k * VV + m] : 0.f;
    PW[pk_b16(k, m, 128)] = __float2half_rn(v);
}

// ---------------- embedding --------------------------------------------------
__global__ void k_embed(const int* __restrict__ idx, const float* __restrict__ tok,
                        const float* __restrict__ pos, float* __restrict__ x) {
    int i = blockIdx.x * blockDim.x + threadIdx.x;
    if (i >= NTOK * EE) return;
    int n = i / EE, e = i - n * EE;
    int t = n % TT;
    x[i] = tok[idx[n] * EE + e] + pos[t * EE + e];
}

// ---------------- LayerNorm (fp32 in, packed fp16 out) -----------------------
__global__ void k_ln(const float* __restrict__ x, const float* __restrict__ g,
                     const float* __restrict__ b, __half* __restrict__ y) {
    int warp = threadIdx.x >> 5, lane = threadIdx.x & 31;
    int row = blockIdx.x * 8 + warp;
    if (row >= NTOK) return;
    const float4* xr = (const float4*)(x + (size_t)row * EE);
    float4 v[3];
#pragma unroll
    for (int i = 0; i < 3; i++) v[i] = xr[lane + i * 32];
    float s = 0.f, s2 = 0.f;
#pragma unroll
    for (int i = 0; i < 3; i++) {
        s  += v[i].x + v[i].y + v[i].z + v[i].w;
        s2 += v[i].x * v[i].x + v[i].y * v[i].y + v[i].z * v[i].z + v[i].w * v[i].w;
    }
#pragma unroll
    for (int off = 16; off > 0; off >>= 1) {
        s  += __shfl_xor_sync(0xffffffffu, s,  off);
        s2 += __shfl_xor_sync(0xffffffffu, s2, off);
    }
    float mu = s * (1.f / EE);
    float var = s2 * (1.f / EE) - mu * mu;
    float rs = rsqrtf(var + 1e-5f);
    const float4* gr = (const float4*)g;
    const float4* br = (const float4*)b;
#pragma unroll
    for (int i = 0; i < 3; i++) {
        float4 gg = gr[lane + i * 32], bb = br[lane + i * 32];
        float o0 = (v[i].x - mu) * rs * gg.x + bb.x;
        float o1 = (v[i].y - mu) * rs * gg.y + bb.y;
        float o2 = (v[i].z - mu) * rs * gg.z + bb.z;
        float o3 = (v[i].w - mu) * rs * gg.w + bb.w;
        int cb = (lane + i * 32) * 4;
        *(__half2*)&y[pk_a16(row, cb,     EE)] = __floats2half2_rn(o0, o1);
        *(__half2*)&y[pk_a16(row, cb + 2, EE)] = __floats2half2_rn(o2, o3);
    }
}

// ---------------- persistent fp16 tensor-core GEMM (64-K slabs) --------------
// flags: 1=relu, 2=packed fp16 out (Ch), 4=natural fp16 out (Ch), else fp32 (Cf)
__global__ void __launch_bounds__(256, 2) k_gemm_h(
    const __half* __restrict__ PA, const __half* __restrict__ PB,
    const float* __restrict__ bias, const float* __restrict__ res,
    float* __restrict__ Cf, __half* __restrict__ Ch,
    int K, int M, int flags, int nTileM, int nTiles)
{
    extern __shared__ __half smh[];
    const int tid  = threadIdx.x;
    const int lane = tid & 31, warp = tid >> 5;
    const int wm = warp & 1, wn = warp >> 1;
    const int gid = lane >> 2, tig = lane & 3;
    const int K16 = K >> 4, M8 = M >> 3;
    const int KB = K >> 6;

    int offA[4], offB[4];
    unsigned sA[4], sB[4];
#pragma unroll
    for (int i = 0; i < 4; i++) {
        int ch = tid + i * 256;
        int mt = ch >> 7, kt = (ch >> 5) & 3, ln = ch & 31;
        sA[i]   = (unsigned)(((mt * 4 + kt) * 256 + ln * 8) * 2);
        offA[i] = (mt * K16 + kt) * 256 + ln * 8;
        int bkt = ch >> 8, rem = ch & 255, nt = rem >> 4, c16 = rem & 15;
        sB[i]   = (unsigned)((8192 + (bkt * 16 + nt) * 128 + c16 * 8) * 2);
        offB[i] = (bkt * M8 + nt) * 128 + c16 * 8;
    }
    unsigned smem_u = (unsigned)__cvta_generic_to_shared(smh);
    const bool relu = (flags & 1), pko = (flags & 2), nat16 = (flags & 4);

    for (int t = blockIdx.x; t < nTiles; t += gridDim.x) {
        const int m0 = (t % nTileM) << 7;
        const int n0 = (t / nTileM) << 7;
        const __half* Abase = PA + (size_t)n0 * K;
        const __half* Bbase = PB + (size_t)(m0 >> 3) * 128;

        auto issue = [&](int ks, int buf) {
            unsigned base = smem_u + (unsigned)buf * 32768u;
#pragma unroll
            for (int i = 0; i < 4; i++) cpa16(base + sA[i], Abase + offA[i] + ks * 1024);
#pragma unroll
            for (int i = 0; i < 4; i++) cpa16(base + sB[i], Bbase + offB[i] + (size_t)ks * 64 * M);
        };

        float acc[4][4][4];
#pragma unroll
        for (int a = 0; a < 4; a++)
#pragma unroll
            for (int b = 0; b < 4; b++)
#pragma unroll
                for (int c = 0; c < 4; c++) acc[a][b][c] = 0.f;

        issue(0, 0);
        asm volatile("cp.async.commit_group;" ::: "memory");
        if (KB > 1) issue(1, 1);
        asm volatile("cp.async.commit_group;" ::: "memory");

        int p = 0;
        for (int kb = 0; kb < KB; kb++) {
            asm volatile("cp.async.wait_group 1;" ::: "memory");
            __syncthreads();
            if (kb + 2 < KB) issue(kb + 2, (kb + 2) % 3);
            asm volatile("cp.async.commit_group;" ::: "memory");

            const __half* as = smh + (size_t)p * 16384;
            const __half* bs = as + 8192;
#pragma unroll
            for (int kt = 0; kt < 4; kt++) {
                unsigned af[4][4], bf[4][2];
#pragma unroll
                for (int mi = 0; mi < 4; mi++) {
                    uint4 v = *(const uint4*)&as[(((wm * 4 + mi) * 4 + kt) * 256) + lane * 8];
                    af[mi][0] = v.x; af[mi][1] = v.y; af[mi][2] = v.z; af[mi][3] = v.w;
                }
#pragma unroll
                for (int ni = 0; ni < 4; ni++) {
                    uint2 v = *(const uint2*)&bs[((kt * 16 + wn * 4 + ni) * 128) + lane * 4];
                    bf[ni][0] = v.x; bf[ni][1] = v.y;
                }
#pragma unroll
                for (int mi = 0; mi < 4; mi++)
#pragma unroll
                    for (int ni = 0; ni < 4; ni++)
                        MMA_F16(acc[mi][ni], af[mi], bf[ni]);
            }
            p = (p == 2) ? 0 : p + 1;
        }
        asm volatile("cp.async.wait_group 0;" ::: "memory");

#pragma unroll
        for (int mi = 0; mi < 4; mi++) {
            int row = n0 + (wm << 6) + (mi << 4) + gid;
#pragma unroll
            for (int ni = 0; ni < 4; ni++) {
                int col = m0 + (wn << 5) + (ni << 3) + (tig << 1);
                float b0 = 0.f, b1 = 0.f;
                if (bias) { b0 = bias[col]; b1 = bias[col + 1]; }
                float v0 = acc[mi][ni][0] + b0;
                float v1 = acc[mi][ni][1] + b1;
                float v2 = acc[mi][ni][2] + b0;
                float v3 = acc[mi][ni][3] + b1;
                if (res) {
                    const float* r0 = res + (size_t)row * M + col;
                    const float* r1 = res + (size_t)(row + 8) * M + col;
                    v0 += r0[0]; v1 += r0[1]; v2 += r1[0]; v3 += r1[1];
                }
                if (relu) {
                    v0 = fmaxf(v0, 0.f); v1 = fmaxf(v1, 0.f);
                    v2 = fmaxf(v2, 0.f); v3 = fmaxf(v3, 0.f);
                }
                if (pko) {
                    *(__half2*)&Ch[pk_a16(row,     col, M)] = __floats2half2_rn(v0, v1);
                    *(__half2*)&Ch[pk_a16(row + 8, col, M)] = __floats2half2_rn(v2, v3);
                } else if (nat16) {
                    *(__half2*)&Ch[(size_t)row * M + col]       = __floats2half2_rn(v0, v1);
                    *(__half2*)&Ch[(size_t)(row + 8) * M + col] = __floats2half2_rn(v2, v3);
                } else {
                    *(float2*)(Cf + (size_t)row * M + col)       = make_float2(v0, v1);
                    *(float2*)(Cf + (size_t)(row + 8) * M + col) = make_float2(v2, v3);
                }
            }
        }
        __syncthreads();
    }
}

// ---------------- tensor-core causal flash attention -------------------------
// Block per (b,h). K,V (256x64 fp16) staged in smem in pk_b16 B-frag layout.
// Warp w owns query tiles {w, 15-w}: exactly 5 key-blocks of 64 each (balanced).
// S = Q K^T via m16n8k16 (fp32 acc), register softmax, P(fp16) V via mma.
__global__ void __launch_bounds__(256) k_attn_mma(
    const __half* __restrict__ QKV, __half* __restrict__ O)
{
    extern __shared__ __half sm[];          // Ksm [64x256] 16K halves, Vsm [256x64] 16K
    __half* Ksm = sm;
    __half* Vsm = sm + 16384;
    const int hd = blockIdx.x, b = blockIdx.y;
    const int tid = threadIdx.x, warp = tid >> 5, lane = tid & 31;
    const int gid = lane >> 2, tig = lane & 3;
    const size_t rowQ = (size_t)(b * TT) * QKVM + hd * DD;   // head-offset base
    const float scale = 0.125f;

    // stage K: B[k=d, n=key] = K[key][d] -> pk_b16(d, key, 256)
    for (int i = tid; i < 256 * 32; i += 256) {
        int key = i >> 5, dp = (i & 31) << 1;
        __half2 v = *(const __half2*)&QKV[rowQ + (size_t)key * QKVM + EE + dp];
        *(__half2*)&Ksm[pk_b16(dp, key, 256)] = v;
    }
    // stage V: B[k=key, n=d] = V[key][d] -> pk_b16(key, d, 64)
    for (int i = tid; i < 256 * 32; i += 256) {
        int key = i >> 5, dp = (i & 31) << 1;
        __half2 v = *(const __half2*)&QKV[rowQ + (size_t)key * QKVM + 2 * EE + dp];
        Vsm[pk_b16(key, dp,     64)] = __low2half(v);
        Vsm[pk_b16(key, dp + 1, 64)] = __high2half(v);
    }
    __syncthreads();

#pragma unroll
    for (int tt = 0; tt < 2; tt++) {
        const int qt = tt ? (15 - warp) : warp;
        const int qbase = qt << 4;
        const int nkb = (qt >> 2) + 1;
        const int qA = qbase + gid, qB = qA + 8;

        // Q A-frags: 4 k-steps x 4 regs (half2). rowQ already head-offset.
        unsigned qf[4][4];
#pragma unroll
        for (int s = 0; s < 4; s++) {
            int d0 = s * 16 + 2 * tig;
            qf[s][0] = *(const unsigned*)&QKV[rowQ + (size_t)qA * QKVM + d0];
            qf[s][1] = *(const unsigned*)&QKV[rowQ + (size_t)qB * QKVM + d0];
            qf[s][2] = *(const unsigned*)&QKV[rowQ + (size_t)qA * QKVM + d0 + 8];
            qf[s][3] = *(const unsigned*)&QKV[rowQ + (size_t)qB * QKVM + d0 + 8];
        }

        float oacc[8][4];
#pragma unroll
        for (int j = 0; j < 8; j++)
#pragma unroll
            for (int t = 0; t < 4; t++) oacc[j][t] = 0.f;
        float mA = -1e30f, mB = -1e30f, lA = 0.f, lB = 0.f;

        for (int kb = 0; kb < nkb; kb++) {
            float sacc[8][4];
#pragma unroll
            for (int j = 0; j < 8; j++)
#pragma unroll
                for (int t = 0; t < 4; t++) sacc[j][t] = 0.f;
#pragma unroll
            for (int s = 0; s < 4; s++) {
#pragma unroll
                for (int j = 0; j < 8; j++) {
                    unsigned kf[2];
                    *(uint2*)kf = *(const uint2*)&Ksm[((s * 32) + (kb * 8 + j)) * 128 + lane * 4];
                    MMA_F16(sacc[j], qf[s], kf);
                }
            }
            // scale + causal mask (only last kb can contain key > q)
            if (kb == nkb - 1) {
#pragma unroll
                for (int j = 0; j < 8; j++) {
                    int k0 = kb * 64 + 8 * j + 2 * tig;
                    sacc[j][0] = (k0     <= qA) ? sacc[j][0] * scale : -1e30f;
                    sacc[j][1] = (k0 + 1 <= qA) ? sacc[j][1] * scale : -1e30f;
                    sacc[j][2] = (k0     <= qB) ? sacc[j][2] * scale : -1e30f;
                    sacc[j][3] = (k0 + 1 <= qB) ? sacc[j][3] * scale : -1e30f;
                }
            } else {
#pragma unroll
                for (int j = 0; j < 8; j++)
#pragma unroll
                    for (int t = 0; t < 4; t++) sacc[j][t] *= scale;
            }
            // row max
            float rA = -1e30f, rB = -1e30f;
#pragma unroll
            for (int j = 0; j < 8; j++) {
                rA = fmaxf(rA, fmaxf(sacc[j][0], sacc[j][1]));
                rB = fmaxf(rB, fmaxf(sacc[j][2], sacc[j][3]));
            }
            rA = fmaxf(rA, __shfl_xor_sync(0xffffffffu, rA, 1));
            rA = fmaxf(rA, __shfl_xor_sync(0xffffffffu, rA, 2));
            rB = fmaxf(rB, __shfl_xor_sync(0xffffffffu, rB, 1));
            rB = fmaxf(rB, __shfl_xor_sync(0xffffffffu, rB, 2));
            float mnA = fmaxf(mA, rA), mnB = fmaxf(mB, rB);
            float alA = __expf(mA - mnA), alB = __expf(mB - mnB);
            mA = mnA; mB = mnB;

            // exp + rowsum + pack P to A-frags
            unsigned pa[4][4];
            float sumA = 0.f, sumB = 0.f;
#pragma unroll
            for (int j = 0; j < 8; j++) {
                float p0 = __expf(sacc[j][0] - mnA);
                float p1 = __expf(sacc[j][1] - mnA);
                float p2 = __expf(sacc[j][2] - mnB);
                float p3 = __expf(sacc[j][3] - mnB);
                sumA += p0 + p1; sumB += p2 + p3;
                __half2 hA = __floats2half2_rn(p0, p1);
                __half2 hB = __floats2half2_rn(p2, p3);
                int s = j >> 1, hi = (j & 1) << 1;
                pa[s][hi]     = *(unsigned*)&hA;
                pa[s][hi + 1] = *(unsigned*)&hB;
            }
            sumA += __shfl_xor_sync(0xffffffffu, sumA, 1);
            sumA += __shfl_xor_sync(0xffffffffu, sumA, 2);
            sumB += __shfl_xor_sync(0xffffffffu, sumB, 1);
            sumB += __shfl_xor_sync(0xffffffffu, sumB, 2);
            lA = lA * alA + sumA;
            lB = lB * alB + sumB;
#pragma unroll
            for (int j = 0; j < 8; j++) {
                oacc[j][0] *= alA; oacc[j][1] *= alA;
                oacc[j][2] *= alB; oacc[j][3] *= alB;
            }
            // O += P @ V
#pragma unroll
            for (int s = 0; s < 4; s++) {
#pragma unroll
                for (int j = 0; j < 8; j++) {
                    unsigned vf[2];
                    *(uint2*)vf = *(const uint2*)&Vsm[((kb * 4 + s) * 8 + j) * 128 + lane * 4];
                    MMA_F16(oacc[j], pa[s], vf);
                }
            }
        }
        float invA = 1.f / lA, invB = 1.f / lB;
        int rA = b * TT + qA, rB = b * TT + qB;
#pragma unroll
        for (int j = 0; j < 8; j++) {
            int cb = hd * DD + 8 * j + 2 * tig;
            *(__half2*)&O[pk_a16(rA, cb, EE)] =
                __floats2half2_rn(oacc[j][0] * invA, oacc[j][1] * invA);
            *(__half2*)&O[pk_a16(rB, cb, EE)] =
                __floats2half2_rn(oacc[j][2] * invB, oacc[j][3] * invB);
        }
    }
}

// ---------------- LM head compact --------------------------------------------
__global__ void k_head_compact(const float* __restrict__ C128,
                               const float* __restrict__ blm,
                               float* __restrict__ logits) {
    int i = blockIdx.x * blockDim.x + threadIdx.x;
    if (i >= NTOK * VV) return;
    int n = i / VV, m = i - n * VV;
    logits[i] = C128[(size_t)n * 128 + m] + blm[m];
}

// ---------------- loss -------------------------------------------------------
__global__ void k_zero(float* loss) { *loss = 0.f; }

__global__ void k_loss(const float* __restrict__ logits, const int* __restrict__ tgt,
                       float* __restrict__ loss) {
    int warp = threadIdx.x >> 5, lane = threadIdx.x & 31;
    int row = blockIdx.x * 8 + warp;
    if (row >= NTOK) return;
    const float* lr = logits + (size_t)row * VV;
    float x0 = (lane < VV)      ? lr[lane]      : -INFINITY;
    float x1 = (lane + 32 < VV) ? lr[lane + 32] : -INFINITY;
    float x2 = (lane + 64 < VV) ? lr[lane + 64] : -INFINITY;
    float mx = fmaxf(x0, fmaxf(x1, x2));
#pragma unroll
    for (int off = 16; off > 0; off >>= 1) mx = fmaxf(mx, __shfl_xor_sync(0xffffffffu, mx, off));
    float se = 0.f;
    if (lane < VV)      se += expf(x0 - mx);
    if (lane + 32 < VV) se += expf(x1 - mx);
    if (lane + 64 < VV) se += expf(x2 - mx);
#pragma unroll
    for (int off = 16; off > 0; off >>= 1) se += __shfl_xor_sync(0xffffffffu, se, off);
    if (lane == 0) {
        float lt = lr[tgt[row]];
        atomicAdd(loss, mx + logf(se) - lt);
    }
}

__global__ void k_final(const float* __restrict__ loss, float* __restrict__ out) {
    out[0] = *loss * (1.f / NTOK);
}

// ---------------- host -------------------------------------------------------
extern "C" void kernel_launch(void* const* d_in, const int* in_sizes, int n_in,
                              void* d_out, int out_size) {
    const int*   idx  = (const int*)  d_in[0];
    const int*   tgt  = (const int*)  d_in[1];
    const float* tok  = (const float*)d_in[2];
    const float* pos  = (const float*)d_in[3];
    const float* Wq   = (const float*)d_in[4];
    const float* Wk   = (const float*)d_in[5];
    const float* Wv   = (const float*)d_in[6];
    const float* Wo   = (const float*)d_in[7];
    const float* bo   = (const float*)d_in[8];
    const float* W1   = (const float*)d_in[9];
    const float* b1   = (const float*)d_in[10];
    const float* W2   = (const float*)d_in[11];
    const float* b2w  = (const float*)d_in[12];
    const float* ln1g = (const float*)d_in[13];
    const float* ln1b = (const float*)d_in[14];
    const float* ln2g = (const float*)d_in[15];
    const float* ln2b = (const float*)d_in[16];
    const float* lnfg = (const float*)d_in[17];
    const float* lnfb = (const float*)d_in[18];
    const float* Wlm  = (const float*)d_in[19];
    const float* blm  = (const float*)d_in[20];

    float *x, *hd, *glog, *gloss;
    __half *h16, *qkv16, *att16, *f16, *pw;
    cudaGetSymbolAddress((void**)&x,     g_x);
    cudaGetSymbolAddress((void**)&h16,   g_h16);
    cudaGetSymbolAddress((void**)&qkv16, g_qkv);
    cudaGetSymbolAddress((void**)&att16, g_att16);
    cudaGetSymbolAddress((void**)&f16,   g_f16);
    cudaGetSymbolAddress((void**)&hd,    g_hd);
    cudaGetSymbolAddress((void**)&glog,  g_logits);
    cudaGetSymbolAddress((void**)&gloss, g_loss);
    cudaGetSymbolAddress((void**)&pw,    g_pw16);

    static int smem_set = 0;
    const int DSM  = 98304;   // GEMM: 3 stages x 32KB
    const int DSMA = 65536;   // attention: K + V staging
    if (!smem_set) {
        cudaFuncSetAttribute(k_gemm_h, cudaFuncAttributeMaxDynamicSharedMemorySize, DSM);
        cudaFuncSetAttribute(k_attn_mma, cudaFuncAttributeMaxDynamicSharedMemorySize, DSMA);
        smem_set = 1;
    }

    const size_t EExEE = (size_t)EE * EE, EExFF = (size_t)EE * FF, EExQ = (size_t)EE * QKVM;
    __half* pqkv = pw;
    __half* pwo  = pqkv + (size_t)LLAY * EExQ;
    __half* pw1  = pwo  + (size_t)LLAY * EExEE;
    __half* pw2  = pw1  + (size_t)LLAY * EExFF;
    __half* pwlm = pw2  + (size_t)LLAY * EExFF;

    k_packQKV<<<dim3((EE * QKVM + 255) / 256, LLAY), 256>>>(Wq, Wk, Wv, pqkv);
    k_packW<<<dim3((EE * EE + 255) / 256, LLAY), 256>>>(Wo, pwo, EE, EE);
    k_packW<<<dim3((EE * FF + 255) / 256, LLAY), 256>>>(W1, pw1, EE, FF);
    k_packW<<<dim3((EE * FF + 255) / 256, LLAY), 256>>>(W2, pw2, FF, EE);
    k_packWlm<<<(EE * 128 + 255) / 256, 256>>>(Wlm, pwlm);

    float* outf   = (float*)d_out;
    float* logits = (out_size >= NTOK * VV) ? outf : glog;

    k_embed<<<(NTOK * EE + 255) / 256, 256>>>(idx, tok, pos, x);

    const int nRow = NTOK / 128;              // 128
    const int tQ = (QKVM / 128) * nRow;       // 1152
    const int tE = (EE / 128) * nRow;         // 384
    const int tF = (FF / 128) * nRow;         // 1536
    dim3 gLN(NTOK / 8);

    for (int l = 0; l < LLAY; l++) {
        k_ln<<<gLN, 256>>>(x, ln1g + l * EE, ln1b + l * EE, h16);
        k_gemm_h<<<GEMM_GRID, 256, DSM>>>(h16, pqkv + (size_t)l * EExQ, nullptr, nullptr,
                                          nullptr, qkv16, EE, QKVM, 4, QKVM / 128, tQ);
        k_attn_mma<<<dim3(HH, BB), 256, DSMA>>>(qkv16, att16);
        k_gemm_h<<<GEMM_GRID, 256, DSM>>>(att16, pwo + (size_t)l * EExEE, bo + l * EE, x,
                                          x, nullptr, EE, EE, 0, EE / 128, tE);
        k_ln<<<gLN, 256>>>(x, ln2g + l * EE, ln2b + l * EE, h16);
        k_gemm_h<<<GEMM_GRID, 256, DSM>>>(h16, pw1 + (size_t)l * EExFF, b1 + l * FF, nullptr,
                                          nullptr, f16, EE, FF, 1 | 2, FF / 128, tF);
        k_gemm_h<<<GEMM_GRID, 256, DSM>>>(f16, pw2 + (size_t)l * EExFF, b2w + l * EE, x,
                                          x, nullptr, FF, EE, 0, EE / 128, tE);
    }

    k_ln<<<gLN, 256>>>(x, lnfg, lnfb, h16);
    k_gemm_h<<<GEMM_GRID, 256, DSM>>>(h16, pwlm, nullptr, nullptr,
                                      hd, nullptr, EE, 128, 0, 1, nRow);
    k_head_compact<<<(NTOK * VV + 255) / 256, 256>>>(hd, blm, logits);

    if (out_size == 1 || out_size > NTOK * VV) {
        k_zero<<<1, 1>>>(gloss);
        k_loss<<<NTOK / 8, 256>>>(logits, tgt, gloss);
        float* ldst = (out_size == 1) ? outf : (outf + NTOK * VV);
        k_final<<<1, 1>>>(gloss, ldst);
    }
}

// round 17
// speedup vs baseline: 2.4022x; 1.0592x over previous
#include <cuda_runtime.h>
#include <cuda_fp16.h>
#include <math.h>

// Problem constants
static const int BB = 64, TT = 256, VV = 65, EE = 384, HH = 6, LLAY = 6, DD = 64, FF = 1536;
static const int NTOK = BB * TT; // 16384
static const int QKVM = 3 * EE;  // 1152
static const int GEMM_GRID = 296;

// ---------------- scratch ----------------------------------------------------
__device__ __align__(16) float  g_x   [16384 * 384];
__device__ __align__(16) __half g_h16 [16384 * 384];    // packed LN output
__device__ __align__(16) __half g_qkv [16384 * 1152];   // natural fp16, stride 1152
__device__ __align__(16) __half g_att16[16384 * 384];   // packed
__device__ __align__(16) __half g_f16 [16384 * 1536];   // packed FFN mid
__device__ __align__(16) float  g_logits[16384 * 65];
__device__ __align__(16) float  g_loss[1];
__device__ __align__(16) __half g_pw16[10665984];

// ---------------- fp16 m16n8k16 fragment-packed indices ----------------------
__device__ __forceinline__ size_t pk_a16(int row, int col, int K) {
    return ((size_t)(row >> 4) * (K >> 4) + (col >> 4)) * 256
         + ((row & 7) * 4 + ((col & 7) >> 1)) * 8
         + (((col >> 3) & 1) * 2 + ((row >> 3) & 1)) * 2 + (col & 1);
}
__device__ __forceinline__ size_t pk_b16(int k, int m, int M) {
    return ((size_t)(k >> 4) * (M >> 3) + (m >> 3)) * 128
         + ((m & 7) * 4 + ((k & 7) >> 1)) * 4
         + ((k >> 3) & 1) * 2 + (k & 1);
}
__device__ __forceinline__ void cpa16(unsigned s, const void* g) {
    asm volatile("cp.async.cg.shared.global [%0], [%1], 16;" :: "r"(s), "l"(g));
}
#define MMA_F16(acc, a, b) \
    asm volatile("mma.sync.aligned.m16n8k16.row.col.f32.f16.f16.f32 " \
        "{%0,%1,%2,%3}, {%4,%5,%6,%7}, {%8,%9}, {%0,%1,%2,%3};" \
        : "+f"((acc)[0]), "+f"((acc)[1]), "+f"((acc)[2]), "+f"((acc)[3]) \
        : "r"((a)[0]), "r"((a)[1]), "r"((a)[2]), "r"((a)[3]), \
          "r"((b)[0]), "r"((b)[1]))

// ---------------- weight pre-pack (k-pair vectorized) ------------------------
__global__ void k_packW(const float* __restrict__ W, __half* __restrict__ PW,
                        int K, int M) {
    int i = blockIdx.x * blockDim.x + threadIdx.x;
    int tot = (K >> 1) * M;
    if (i >= tot) return;
    const float* w = W + (size_t)blockIdx.y * K * M;
    __half* pw = PW + (size_t)blockIdx.y * K * M;
    int k2 = i / M, m = i - k2 * M;
    int k = k2 << 1;
    __half2 v = __floats2half2_rn(w[(size_t)k * M + m], w[(size_t)(k + 1) * M + m]);
    *(__half2*)&pw[pk_b16(k, m, M)] = v;
}
__global__ void k_packQKV(const float* __restrict__ Wq, const float* __restrict__ Wk,
                          const float* __restrict__ Wv, __half* __restrict__ PW) {
    int i = blockIdx.x * blockDim.x + threadIdx.x;
    const int tot = (EE >> 1) * QKVM;
    if (i >= tot) return;
    int l = blockIdx.y;
    int k2 = i / QKVM, m = i - k2 * QKVM;
    int k = k2 << 1;
    const float* src; int mm;
    if (m < EE)          { src = Wq; mm = m; }
    else if (m < 2 * EE) { src = Wk; mm = m - EE; }
    else                 { src = Wv; mm = m - 2 * EE; }
    src += (size_t)l * EE * EE;
    __half2 v = __floats2half2_rn(src[(size_t)k * EE + mm], src[(size_t)(k + 1) * EE + mm]);
    *(__half2*)&PW[(size_t)l * EE * QKVM + pk_b16(k, m, QKVM)] = v;
}
__global__ void k_packWlm(const float* __restrict__ W, __half* __restrict__ PW) {
    int i = blockIdx.x * blockDim.x + threadIdx.x;
    if (i >= (EE >> 1) * 128) return;
    int k2 = i >> 7, m = i & 127;
    int k = k2 << 1;
    float v0 = (m < VV) ? W[(size_t)k * VV + m] : 0.f;
    float v1 = (m < VV) ? W[(size_t)(k + 1) * VV + m] : 0.f;
    *(__half2*)&PW[pk_b16(k, m, 128)] = __floats2half2_rn(v0, v1);
}

// ---------------- embedding --------------------------------------------------
__global__ void k_embed(const int* __restrict__ idx, const float* __restrict__ tok,
                        const float* __restrict__ pos, float* __restrict__ x) {
    int i = blockIdx.x * blockDim.x + threadIdx.x;
    if (i >= NTOK * EE) return;
    int n = i / EE, e = i - n * EE;
    int t = n % TT;
    x[i] = tok[idx[n] * EE + e] + pos[t * EE + e];
}

// ---------------- LayerNorm: 16-row tile, smem-staged, 16B fragment stores ---
__global__ void __launch_bounds__(256) k_ln(
    const float* __restrict__ x, const float* __restrict__ g,
    const float* __restrict__ b, __half* __restrict__ y) {
    __shared__ float xs[16][384];
    const int tid = threadIdx.x, warp = tid >> 5, lane = tid & 31;
    const int rt = blockIdx.x;               // row tile (16 rows)
    // load 16x384 fp32 coalesced
    const float4* xg = (const float4*)(x + (size_t)rt * 16 * EE);
    float4* xs4 = (float4*)&xs[0][0];
#pragma unroll
    for (int i = 0; i < 6; i++) xs4[tid + i * 256] = xg[tid + i * 256];
    __syncthreads();
    // warp w reduces rows w and w+8
    float s0 = 0.f, q0 = 0.f, s1 = 0.f, q1 = 0.f;
    const float4* r0 = (const float4*)&xs[warp][0];
    const float4* r1 = (const float4*)&xs[warp + 8][0];
#pragma unroll
    for (int i = 0; i < 3; i++) {
        float4 v = r0[lane + i * 32];
        s0 += v.x + v.y + v.z + v.w;
        q0 += v.x * v.x + v.y * v.y + v.z * v.z + v.w * v.w;
        float4 u = r1[lane + i * 32];
        s1 += u.x + u.y + u.z + u.w;
        q1 += u.x * u.x + u.y * u.y + u.z * u.z + u.w * u.w;
    }
#pragma unroll
    for (int off = 16; off > 0; off >>= 1) {
        s0 += __shfl_xor_sync(0xffffffffu, s0, off);
        q0 += __shfl_xor_sync(0xffffffffu, q0, off);
        s1 += __shfl_xor_sync(0xffffffffu, s1, off);
        q1 += __shfl_xor_sync(0xffffffffu, q1, off);
    }
    float mu0 = s0 * (1.f / EE), mu1 = s1 * (1.f / EE);
    float rs0 = rsqrtf(q0 * (1.f / EE) - mu0 * mu0 + 1e-5f);
    float rs1 = rsqrtf(q1 * (1.f / EE) - mu1 * mu1 + 1e-5f);
    // write: quad groups q=lane,+32,+64; group = rows {w,w+8} x cols {c0,c0+1,c0+8,c0+9}
    __half* yt = y + (size_t)rt * 24 * 256;
#pragma unroll
    for (int i = 0; i < 3; i++) {
        int q = lane + i * 32;
        int t = q >> 2, qc = q & 3;
        int c0 = t * 16 + qc * 2;
        float g0 = g[c0], g1 = g[c0 + 1], g8 = g[c0 + 8], g9 = g[c0 + 9];
        float b0 = b[c0], b1 = b[c0 + 1], b8 = b[c0 + 8], b9 = b[c0 + 9];
        __half2 h[4];
        h[0] = __floats2half2_rn((xs[warp][c0]     - mu0) * rs0 * g0 + b0,
                                 (xs[warp][c0 + 1] - mu0) * rs0 * g1 + b1);
        h[1] = __floats2half2_rn((xs[warp + 8][c0]     - mu1) * rs1 * g0 + b0,
                                 (xs[warp + 8][c0 + 1] - mu1) * rs1 * g1 + b1);
        h[2] = __floats2half2_rn((xs[warp][c0 + 8] - mu0) * rs0 * g8 + b8,
                                 (xs[warp][c0 + 9] - mu0) * rs0 * g9 + b9);
        h[3] = __floats2half2_rn((xs[warp + 8][c0 + 8] - mu1) * rs1 * g8 + b8,
                                 (xs[warp + 8][c0 + 9] - mu1) * rs1 * g9 + b9);
        *(uint4*)&yt[(size_t)t * 256 + (warp * 4 + qc) * 8] = *(uint4*)h;
    }
}

// ---------------- persistent fp16 tensor-core GEMM (64-K slabs) --------------
// flags: 1=relu, 2=packed fp16 out (Ch), 4=natural fp16 out (Ch),
//        8=logits out (Cf stride VV, col<VV guard, bias guarded), else fp32
__global__ void __launch_bounds__(256, 2) k_gemm_h(
    const __half* __restrict__ PA, const __half* __restrict__ PB,
    const float* __restrict__ bias, const float* __restrict__ res,
    float* __restrict__ Cf, __half* __restrict__ Ch,
    int K, int M, int flags, int nTileM, int nTiles)
{
    extern __shared__ __half smh[];
    const int tid  = threadIdx.x;
    const int lane = tid & 31, warp = tid >> 5;
    const int wm = warp & 1, wn = warp >> 1;
    const int gid = lane >> 2, tig = lane & 3;
    const int K16 = K >> 4, M8 = M >> 3;
    const int KB = K >> 6;

    int offA[4], offB[4];
    unsigned sA[4], sB[4];
#pragma unroll
    for (int i = 0; i < 4; i++) {
        int ch = tid + i * 256;
        int mt = ch >> 7, kt = (ch >> 5) & 3, ln = ch & 31;
        sA[i]   = (unsigned)(((mt * 4 + kt) * 256 + ln * 8) * 2);
        offA[i] = (mt * K16 + kt) * 256 + ln * 8;
        int bkt = ch >> 8, rem = ch & 255, nt = rem >> 4, c16 = rem & 15;
        sB[i]   = (unsigned)((8192 + (bkt * 16 + nt) * 128 + c16 * 8) * 2);
        offB[i] = (bkt * M8 + nt) * 128 + c16 * 8;
    }
    unsigned smem_u = (unsigned)__cvta_generic_to_shared(smh);
    const bool relu = (flags & 1), pko = (flags & 2), nat16 = (flags & 4), lgts = (flags & 8);

    for (int t = blockIdx.x; t < nTiles; t += gridDim.x) {
        const int m0 = (t % nTileM) << 7;
        const int n0 = (t / nTileM) << 7;
        const __half* Abase = PA + (size_t)n0 * K;
        const __half* Bbase = PB + (size_t)(m0 >> 3) * 128;

        auto issue = [&](int ks, int buf) {
            unsigned base = smem_u + (unsigned)buf * 32768u;
#pragma unroll
            for (int i = 0; i < 4; i++) cpa16(base + sA[i], Abase + offA[i] + ks * 1024);
#pragma unroll
            for (int i = 0; i < 4; i++) cpa16(base + sB[i], Bbase + offB[i] + (size_t)ks * 64 * M);
        };

        float acc[4][4][4];
#pragma unroll
        for (int a = 0; a < 4; a++)
#pragma unroll
            for (int b = 0; b < 4; b++)
#pragma unroll
                for (int c = 0; c < 4; c++) acc[a][b][c] = 0.f;

        issue(0, 0);
        asm volatile("cp.async.commit_group;" ::: "memory");
        if (KB > 1) issue(1, 1);
        asm volatile("cp.async.commit_group;" ::: "memory");

        int p = 0;
        for (int kb = 0; kb < KB; kb++) {
            asm volatile("cp.async.wait_group 1;" ::: "memory");
            __syncthreads();
            if (kb + 2 < KB) issue(kb + 2, (kb + 2) % 3);
            asm volatile("cp.async.commit_group;" ::: "memory");

            const __half* as = smh + (size_t)p * 16384;
            const __half* bs = as + 8192;
#pragma unroll
            for (int kt = 0; kt < 4; kt++) {
                unsigned af[4][4], bf[4][2];
#pragma unroll
                for (int mi = 0; mi < 4; mi++) {
                    uint4 v = *(const uint4*)&as[(((wm * 4 + mi) * 4 + kt) * 256) + lane * 8];
                    af[mi][0] = v.x; af[mi][1] = v.y; af[mi][2] = v.z; af[mi][3] = v.w;
                }
#pragma unroll
                for (int ni = 0; ni < 4; ni++) {
                    uint2 v = *(const uint2*)&bs[((kt * 16 + wn * 4 + ni) * 128) + lane * 4];
                    bf[ni][0] = v.x; bf[ni][1] = v.y;
                }
#pragma unroll
                for (int mi = 0; mi < 4; mi++)
#pragma unroll
                    for (int ni = 0; ni < 4; ni++)
                        MMA_F16(acc[mi][ni], af[mi], bf[ni]);
            }
            p = (p == 2) ? 0 : p + 1;
        }
        asm volatile("cp.async.wait_group 0;" ::: "memory");

#pragma unroll
        for (int mi = 0; mi < 4; mi++) {
            int row = n0 + (wm << 6) + (mi << 4) + gid;
            if (pko) {
                // 16B fragment-group stores: pair (ni, ni+1)
#pragma unroll
                for (int ni = 0; ni < 4; ni += 2) {
                    int c0 = m0 + (wn << 5) + (ni << 3) + (tig << 1);
                    float b0 = 0.f, b1 = 0.f, b8 = 0.f, b9 = 0.f;
                    if (bias) { b0 = bias[c0]; b1 = bias[c0 + 1]; b8 = bias[c0 + 8]; b9 = bias[c0 + 9]; }
                    float v0 = acc[mi][ni][0] + b0,     v1 = acc[mi][ni][1] + b1;
                    float v2 = acc[mi][ni][2] + b0,     v3 = acc[mi][ni][3] + b1;
                    float v4 = acc[mi][ni + 1][0] + b8, v5 = acc[mi][ni + 1][1] + b9;
                    float v6 = acc[mi][ni + 1][2] + b8, v7 = acc[mi][ni + 1][3] + b9;
                    if (relu) {
                        v0 = fmaxf(v0, 0.f); v1 = fmaxf(v1, 0.f); v2 = fmaxf(v2, 0.f); v3 = fmaxf(v3, 0.f);
                        v4 = fmaxf(v4, 0.f); v5 = fmaxf(v5, 0.f); v6 = fmaxf(v6, 0.f); v7 = fmaxf(v7, 0.f);
                    }
                    __half2 h[4];
                    h[0] = __floats2half2_rn(v0, v1);
                    h[1] = __floats2half2_rn(v2, v3);
                    h[2] = __floats2half2_rn(v4, v5);
                    h[3] = __floats2half2_rn(v6, v7);
                    size_t rowt = (size_t)(row >> 4) * (M >> 4) + ((c0 >> 4));
                    *(uint4*)&Ch[rowt * 256 + (gid * 4 + tig) * 8] = *(uint4*)h;
                }
            } else {
#pragma unroll
                for (int ni = 0; ni < 4; ni++) {
                    int col = m0 + (wn << 5) + (ni << 3) + (tig << 1);
                    if (lgts) {
                        float b0 = (col < VV) ? bias[col] : 0.f;
                        float b1 = (col + 1 < VV) ? bias[col + 1] : 0.f;
                        if (col < VV) {
                            Cf[(size_t)row * VV + col]       = acc[mi][ni][0] + b0;
                            Cf[(size_t)(row + 8) * VV + col] = acc[mi][ni][2] + b0;
                        }
                        if (col + 1 < VV) {
                            Cf[(size_t)row * VV + col + 1]       = acc[mi][ni][1] + b1;
                            Cf[(size_t)(row + 8) * VV + col + 1] = acc[mi][ni][3] + b1;
                        }
                        continue;
                    }
                    float b0 = 0.f, b1 = 0.f;
                    if (bias) { b0 = bias[col]; b1 = bias[col + 1]; }
                    float v0 = acc[mi][ni][0] + b0;
                    float v1 = acc[mi][ni][1] + b1;
                    float v2 = acc[mi][ni][2] + b0;
                    float v3 = acc[mi][ni][3] + b1;
                    if (res) {
                        const float* r0 = res + (size_t)row * M + col;
                        const float* r1 = res + (size_t)(row + 8) * M + col;
                        v0 += r0[0]; v1 += r0[1]; v2 += r1[0]; v3 += r1[1];
                    }
                    if (relu) {
                        v0 = fmaxf(v0, 0.f); v1 = fmaxf(v1, 0.f);
                        v2 = fmaxf(v2, 0.f); v3 = fmaxf(v3, 0.f);
                    }
                    if (nat16) {
                        *(__half2*)&Ch[(size_t)row * M + col]       = __floats2half2_rn(v0, v1);
                        *(__half2*)&Ch[(size_t)(row + 8) * M + col] = __floats2half2_rn(v2, v3);
                    } else {
                        *(float2*)(Cf + (size_t)row * M + col)       = make_float2(v0, v1);
                        *(float2*)(Cf + (size_t)(row + 8) * M + col) = make_float2(v2, v3);
                    }
                }
            }
        }
        __syncthreads();
    }
}

// ---------------- tensor-core causal flash attention -------------------------
__global__ void __launch_bounds__(256) k_attn_mma(
    const __half* __restrict__ QKV, __half* __restrict__ O)
{
    extern __shared__ __half sm[];
    __half* Ksm = sm;
    __half* Vsm = sm + 16384;
    const int hd = blockIdx.x, b = blockIdx.y;
    const int tid = threadIdx.x, warp = tid >> 5, lane = tid & 31;
    const int gid = lane >> 2, tig = lane & 3;
    const size_t rowQ = (size_t)(b * TT) * QKVM + hd * DD;
    const float scale = 0.125f;

    for (int i = tid; i < 256 * 32; i += 256) {
        int key = i >> 5, dp = (i & 31) << 1;
        __half2 v = *(const __half2*)&QKV[rowQ + (size_t)key * QKVM + EE + dp];
        *(__half2*)&Ksm[pk_b16(dp, key, 256)] = v;
    }
    for (int i = tid; i < 256 * 32; i += 256) {
        int key = i >> 5, dp = (i & 31) << 1;
        __half2 v = *(const __half2*)&QKV[rowQ + (size_t)key * QKVM + 2 * EE + dp];
        Vsm[pk_b16(key, dp,     64)] = __low2half(v);
        Vsm[pk_b16(key, dp + 1, 64)] = __high2half(v);
    }
    __syncthreads();

#pragma unroll
    for (int tt = 0; tt < 2; tt++) {
        const int qt = tt ? (15 - warp) : warp;
        const int qbase = qt << 4;
        const int nkb = (qt >> 2) + 1;
        const int qA = qbase + gid, qB = qA + 8;

        unsigned qf[4][4];
#pragma unroll
        for (int s = 0; s < 4; s++) {
            int d0 = s * 16 + 2 * tig;
            qf[s][0] = *(const unsigned*)&QKV[rowQ + (size_t)qA * QKVM + d0];
            qf[s][1] = *(const unsigned*)&QKV[rowQ + (size_t)qB * QKVM + d0];
            qf[s][2] = *(const unsigned*)&QKV[rowQ + (size_t)qA * QKVM + d0 + 8];
            qf[s][3] = *(const unsigned*)&QKV[rowQ + (size_t)qB * QKVM + d0 + 8];
        }

        float oacc[8][4];
#pragma unroll
        for (int j = 0; j < 8; j++)
#pragma unroll
            for (int t = 0; t < 4; t++) oacc[j][t] = 0.f;
        float mA = -1e30f, mB = -1e30f, lA = 0.f, lB = 0.f;

        for (int kb = 0; kb < nkb; kb++) {
            float sacc[8][4];
#pragma unroll
            for (int j = 0; j < 8; j++)
#pragma unroll
                for (int t = 0; t < 4; t++) sacc[j][t] = 0.f;
#pragma unroll
            for (int s = 0; s < 4; s++) {
#pragma unroll
                for (int j = 0; j < 8; j++) {
                    unsigned kf[2];
                    *(uint2*)kf = *(const uint2*)&Ksm[((s * 32) + (kb * 8 + j)) * 128 + lane * 4];
                    MMA_F16(sacc[j], qf[s], kf);
                }
            }
            if (kb == nkb - 1) {
#pragma unroll
                for (int j = 0; j < 8; j++) {
                    int k0 = kb * 64 + 8 * j + 2 * tig;
                    sacc[j][0] = (k0     <= qA) ? sacc[j][0] * scale : -1e30f;
                    sacc[j][1] = (k0 + 1 <= qA) ? sacc[j][1] * scale : -1e30f;
                    sacc[j][2] = (k0     <= qB) ? sacc[j][2] * scale : -1e30f;
                    sacc[j][3] = (k0 + 1 <= qB) ? sacc[j][3] * scale : -1e30f;
                }
            } else {
#pragma unroll
                for (int j = 0; j < 8; j++)
#pragma unroll
                    for (int t = 0; t < 4; t++) sacc[j][t] *= scale;
            }
            float rA = -1e30f, rB = -1e30f;
#pragma unroll
            for (int j = 0; j < 8; j++) {
                rA = fmaxf(rA, fmaxf(sacc[j][0], sacc[j][1]));
                rB = fmaxf(rB, fmaxf(sacc[j][2], sacc[j][3]));
            }
            rA = fmaxf(rA, __shfl_xor_sync(0xffffffffu, rA, 1));
            rA = fmaxf(rA, __shfl_xor_sync(0xffffffffu, rA, 2));
            rB = fmaxf(rB, __shfl_xor_sync(0xffffffffu, rB, 1));
            rB = fmaxf(rB, __shfl_xor_sync(0xffffffffu, rB, 2));
            float mnA = fmaxf(mA, rA), mnB = fmaxf(mB, rB);
            float alA = __expf(mA - mnA), alB = __expf(mB - mnB);
            mA = mnA; mB = mnB;

            unsigned pa[4][4];
            float sumA = 0.f, sumB = 0.f;
#pragma unroll
            for (int j = 0; j < 8; j++) {
                float p0 = __expf(sacc[j][0] - mnA);
                float p1 = __expf(sacc[j][1] - mnA);
                float p2 = __expf(sacc[j][2] - mnB);
                float p3 = __expf(sacc[j][3] - mnB);
                sumA += p0 + p1; sumB += p2 + p3;
                __half2 hA = __floats2half2_rn(p0, p1);
                __half2 hB = __floats2half2_rn(p2, p3);
                int s = j >> 1, hi = (j & 1) << 1;
                pa[s][hi]     = *(unsigned*)&hA;
                pa[s][hi + 1] = *(unsigned*)&hB;
            }
            sumA += __shfl_xor_sync(0xffffffffu, sumA, 1);
            sumA += __shfl_xor_sync(0xffffffffu, sumA, 2);
            sumB += __shfl_xor_sync(0xffffffffu, sumB, 1);
            sumB += __shfl_xor_sync(0xffffffffu, sumB, 2);
            lA = lA * alA + sumA;
            lB = lB * alB + sumB;
#pragma unroll
            for (int j = 0; j < 8; j++) {
                oacc[j][0] *= alA; oacc[j][1] *= alA;
                oacc[j][2] *= alB; oacc[j][3] *= alB;
            }
#pragma unroll
            for (int s = 0; s < 4; s++) {
#pragma unroll
                for (int j = 0; j < 8; j++) {
                    unsigned vf[2];
                    *(uint2*)vf = *(const uint2*)&Vsm[((kb * 4 + s) * 8 + j) * 128 + lane * 4];
                    MMA_F16(oacc[j], pa[s], vf);
                }
            }
        }
        float invA = 1.f / lA, invB = 1.f / lB;
        int rA = b * TT + qA, rB = b * TT + qB;
#pragma unroll
        for (int j = 0; j < 8; j++) {
            int cb = hd * DD + 8 * j + 2 * tig;
            *(__half2*)&O[pk_a16(rA, cb, EE)] =
                __floats2half2_rn(oacc[j][0] * invA, oacc[j][1] * invA);
            *(__half2*)&O[pk_a16(rB, cb, EE)] =
                __floats2half2_rn(oacc[j][2] * invB, oacc[j][3] * invB);
        }
    }
}

// ---------------- loss -------------------------------------------------------
__global__ void k_zero(float* loss) { *loss = 0.f; }

__global__ void k_loss(const float* __restrict__ logits, const int* __restrict__ tgt,
                       float* __restrict__ loss) {
    int warp = threadIdx.x >> 5, lane = threadIdx.x & 31;
    int row = blockIdx.x * 8 + warp;
    if (row >= NTOK) return;
    const float* lr = logits + (size_t)row * VV;
    float x0 = (lane < VV)      ? lr[lane]      : -INFINITY;
    float x1 = (lane + 32 < VV) ? lr[lane + 32] : -INFINITY;
    float x2 = (lane + 64 < VV) ? lr[lane + 64] : -INFINITY;
    float mx = fmaxf(x0, fmaxf(x1, x2));
#pragma unroll
    for (int off = 16; off > 0; off >>= 1) mx = fmaxf(mx, __shfl_xor_sync(0xffffffffu, mx, off));
    float se = 0.f;
    if (lane < VV)      se += expf(x0 - mx);
    if (lane + 32 < VV) se += expf(x1 - mx);
    if (lane + 64 < VV) se += expf(x2 - mx);
#pragma unroll
    for (int off = 16; off > 0; off >>= 1) se += __shfl_xor_sync(0xffffffffu, se, off);
    if (lane == 0) {
        float lt = lr[tgt[row]];
        atomicAdd(loss, mx + logf(se) - lt);
    }
}

__global__ void k_final(const float* __restrict__ loss, float* __restrict__ out) {
    out[0] = *loss * (1.f / NTOK);
}

// ---------------- host -------------------------------------------------------
extern "C" void kernel_launch(void* const* d_in, const int* in_sizes, int n_in,
                              void* d_out, int out_size) {
    const int*   idx  = (const int*)  d_in[0];
    const int*   tgt  = (const int*)  d_in[1];
    const float* tok  = (const float*)d_in[2];
    const float* pos  = (const float*)d_in[3];
    const float* Wq   = (const float*)d_in[4];
    const float* Wk   = (const float*)d_in[5];
    const float* Wv   = (const float*)d_in[6];
    const float* Wo   = (const float*)d_in[7];
    const float* bo   = (const float*)d_in[8];
    const float* W1   = (const float*)d_in[9];
    const float* b1   = (const float*)d_in[10];
    const float* W2   = (const float*)d_in[11];
    const float* b2w  = (const float*)d_in[12];
    const float* ln1g = (const float*)d_in[13];
    const float* ln1b = (const float*)d_in[14];
    const float* ln2g = (const float*)d_in[15];
    const float* ln2b = (const float*)d_in[16];
    const float* lnfg = (const float*)d_in[17];
    const float* lnfb = (const float*)d_in[18];
    const float* Wlm  = (const float*)d_in[19];
    const float* blm  = (const float*)d_in[20];

    float *x, *glog, *gloss;
    __half *h16, *qkv16, *att16, *f16, *pw;
    cudaGetSymbolAddress((void**)&x,     g_x);
    cudaGetSymbolAddress((void**)&h16,   g_h16);
    cudaGetSymbolAddress((void**)&qkv16, g_qkv);
    cudaGetSymbolAddress((void**)&att16, g_att16);
    cudaGetSymbolAddress((void**)&f16,   g_f16);
    cudaGetSymbolAddress((void**)&glog,  g_logits);
    cudaGetSymbolAddress((void**)&gloss, g_loss);
    cudaGetSymbolAddress((void**)&pw,    g_pw16);

    static int smem_set = 0;
    const int DSM  = 98304;   // GEMM: 3 stages x 32KB
    const int DSMA = 65536;   // attention: K + V staging
    if (!smem_set) {
        cudaFuncSetAttribute(k_gemm_h, cudaFuncAttributeMaxDynamicSharedMemorySize, DSM);
        cudaFuncSetAttribute(k_attn_mma, cudaFuncAttributeMaxDynamicSharedMemorySize, DSMA);
        smem_set = 1;
    }

    const size_t EExEE = (size_t)EE * EE, EExFF = (size_t)EE * FF, EExQ = (size_t)EE * QKVM;
    __half* pqkv = pw;
    __half* pwo  = pqkv + (size_t)LLAY * EExQ;
    __half* pw1  = pwo  + (size_t)LLAY * EExEE;
    __half* pw2  = pw1  + (size_t)LLAY * EExFF;
    __half* pwlm = pw2  + (size_t)LLAY * EExFF;

    k_packQKV<<<dim3(((EE / 2) * QKVM + 255) / 256, LLAY), 256>>>(Wq, Wk, Wv, pqkv);
    k_packW<<<dim3(((EE / 2) * EE + 255) / 256, LLAY), 256>>>(Wo, pwo, EE, EE);
    k_packW<<<dim3(((EE / 2) * FF + 255) / 256, LLAY), 256>>>(W1, pw1, EE, FF);
    k_packW<<<dim3(((FF / 2) * EE + 255) / 256, LLAY), 256>>>(W2, pw2, FF, EE);
    k_packWlm<<<((EE / 2) * 128 + 255) / 256, 256>>>(Wlm, pwlm);

    float* outf   = (float*)d_out;
    float* logits = (out_size >= NTOK * VV) ? outf : glog;

    k_embed<<<(NTOK * EE + 255) / 256, 256>>>(idx, tok, pos, x);

    const int nRow = NTOK / 128;              // 128
    const int tQ = (QKVM / 128) * nRow;       // 1152
    const int tE = (EE / 128) * nRow;         // 384
    const int tF = (FF / 128) * nRow;         // 1536
    dim3 gLN(NTOK / 16);

    for (int l = 0; l < LLAY; l++) {
        k_ln<<<gLN, 256>>>(x, ln1g + l * EE, ln1b + l * EE, h16);
        k_gemm_h<<<GEMM_GRID, 256, DSM>>>(h16, pqkv + (size_t)l * EExQ, nullptr, nullptr,
                                          nullptr, qkv16, EE, QKVM, 4, QKVM / 128, tQ);
        k_attn_mma<<<dim3(HH, BB), 256, DSMA>>>(qkv16, att16);
        k_gemm_h<<<GEMM_GRID, 256, DSM>>>(att16, pwo + (size_t)l * EExEE, bo + l * EE, x,
                                          x, nullptr, EE, EE, 0, EE / 128, tE);
        k_ln<<<gLN, 256>>>(x, ln2g + l * EE, ln2b + l * EE, h16);
        k_gemm_h<<<GEMM_GRID, 256, DSM>>>(h16, pw1 + (size_t)l * EExFF, b1 + l * FF, nullptr,
                                          nullptr, f16, EE, FF, 1 | 2, FF / 128, tF);
        k_gemm_h<<<GEMM_GRID, 256, DSM>>>(f16, pw2 + (size_t)l * EExFF, b2w + l * EE, x,
                                          x, nullptr, FF, EE, 0, EE / 128, tE);
    }

    k_ln<<<gLN, 256>>>(x, lnfg, lnfb, h16);
    k_gemm_h<<<GEMM_GRID, 256, DSM>>>(h16, pwlm, blm, nullptr,
                                      logits, nullptr, EE, 128, 8, 1, nRow);

    if (out_size == 1 || out_size > NTOK * VV) {
        k_zero<<<1, 1>>>(gloss);
        k_loss<<<NTOK / 8, 256>>>(logits, tgt, gloss);
        float* ldst = (out_size == 1) ? outf : (outf + NTOK * VV);
        k_final<<<1, 1>>>(gloss, ldst);
    }
}